// round 1
// baseline (speedup 1.0000x reference)
#include <cuda_runtime.h>
#include <math.h>

// ---------------- scratch (device globals; no allocation allowed) ----------------
__device__ float g_h1[256 * 14 * 14 * 256];    // conv1+pool out          51.4 MB
__device__ float g_c2[256 * 14 * 14 * 256];    // conv2 pre-pool out      51.4 MB
__device__ float g_h2[256 * 7 * 7 * 256];      // conv2+pool out          12.8 MB
__device__ float g_encp[16 * 256 * 64];        // encoder split-K partials
__device__ float g_z[512 * 64];                // rows 0..255 = z_e, 256..511 = z_q
__device__ float g_d[512 * 7 * 7 * 256];       // decoder FC out (e,q)    25.7 MB
__device__ float g_g1[512 * 14 * 14 * 256];    // deconv1 out (e,q)      102.8 MB

// ---------------- packed f32x2 helpers (sm_103a FFMA2) ----------------
__device__ __forceinline__ unsigned long long splat2(float x) {
    unsigned long long r;
    asm("mov.b64 %0, {%1, %1};" : "=l"(r) : "r"(__float_as_uint(x)));
    return r;
}
__device__ __forceinline__ void ffma2(unsigned long long& c, unsigned long long a,
                                      unsigned long long b) {
    asm("fma.rn.f32x2 %0, %1, %2, %0;" : "+l"(c) : "l"(a), "l"(b));
}
__device__ __forceinline__ float2 unpack2(unsigned long long c) {
    float2 f;
    asm("mov.b64 {%0, %1}, %2;" : "=f"(f.x), "=f"(f.y) : "l"(c));
    return f;
}

// ---------------- K1: conv1 (4x4, 1->256, SAME pad lo=1) + ReLU + maxpool 2x2 ----
// grid (14 = pooled row, 256 = batch), block 256 = out channel
__global__ __launch_bounds__(256) void k_conv1pool(const float* __restrict__ x,
                                                   const float* __restrict__ w1,
                                                   const float* __restrict__ b1) {
    int py = blockIdx.x;
    int b = blockIdx.y;
    int c = threadIdx.x;
    __shared__ float xs[5][32];  // rows 2py-1..2py+3, col index = ix+1 (ix in -1..30)
    for (int e = threadIdx.x; e < 5 * 32; e += 256) {
        int r = e / 32, cc = e % 32;
        int iy = 2 * py - 1 + r;
        int ix = cc - 1;
        float v = 0.f;
        if (iy >= 0 && iy < 28 && ix >= 0 && ix < 28) v = x[(b * 28 + iy) * 28 + ix];
        xs[r][cc] = v;
    }
    float w[16];
#pragma unroll
    for (int i = 0; i < 16; i++) w[i] = w1[i * 256 + c];
    float bias = b1[c];
    __syncthreads();
    for (int px = 0; px < 14; px++) {
        float mv = -1e30f;
#pragma unroll
        for (int dy = 0; dy < 2; dy++)
#pragma unroll
            for (int dx = 0; dx < 2; dx++) {
                float v = bias;
#pragma unroll
                for (int ky = 0; ky < 4; ky++)
#pragma unroll
                    for (int kx = 0; kx < 4; kx++)
                        v += xs[dy + ky][2 * px + dx + kx] * w[ky * 4 + kx];
                mv = fmaxf(mv, v);
            }
        g_h1[((b * 14 + py) * 14 + px) * 256 + c] = fmaxf(mv, 0.f);
    }
}

// ---------------- K2: implicit-GEMM conv 4x4, 256->256, SAME, on 14x14 grid -------
// UPSAMPLE=0: input [NB][14][14][256] read directly (conv2 path)
// UPSAMPLE=1: input [NB][7][7][256], upsample-2x folded into the gather (deconv1)
// Always applies +bias and ReLU. M = NB*196 (multiple of 128), N = 256, K = 4096.
template <int UPSAMPLE>
__global__ __launch_bounds__(256, 2) void k_convgemm(const float* __restrict__ in,
                                                     const float* __restrict__ w,
                                                     const float* __restrict__ bias,
                                                     float* __restrict__ out) {
    const int m0 = blockIdx.x * 128;
    const int n0 = blockIdx.y * 128;
    __shared__ float As[16][128];
    __shared__ float Bs[16][128];
    const int t = threadIdx.x;
    // A loader: thread covers (mm, kk = kh*8 .. kh*8+7)
    const int mm = t & 127;
    const int kh = t >> 7;
    const int m = m0 + mm;
    const int img = m / 196;
    const int p = m % 196;
    const int oy = p / 14;
    const int ox = p % 14;
    // B loader
    const int bn = (t & 15) * 8;
    const int bk = t >> 4;
    // compute mapping: 8x8 micro-tile
    const int tr = t >> 4;
    const int tc = t & 15;

    unsigned long long acc[8][4];
#pragma unroll
    for (int i = 0; i < 8; i++)
#pragma unroll
        for (int j = 0; j < 4; j++) acc[i][j] = 0ull;

    for (int k0 = 0; k0 < 4096; k0 += 16) {
        // gather A (issued before the sync -> overlaps previous tile's math)
        int tap = k0 >> 8;
        int ky = tap >> 2, kx = tap & 3;
        int iy = oy - 1 + ky, ix = ox - 1 + kx;
        float4 a0 = make_float4(0.f, 0.f, 0.f, 0.f), a1 = a0;
        if ((unsigned)iy < 14u && (unsigned)ix < 14u) {
            int ci = (k0 & 255) + kh * 8;
            const float* src;
            if (UPSAMPLE)
                src = in + ((img * 7 + (iy >> 1)) * 7 + (ix >> 1)) * 256 + ci;
            else
                src = in + ((img * 14 + iy) * 14 + ix) * 256 + ci;
            a0 = *(const float4*)src;
            a1 = *(const float4*)(src + 4);
        }
        const float* wsrc = w + (k0 + bk) * 256 + n0 + bn;
        float4 b0 = *(const float4*)wsrc;
        float4 b1 = *(const float4*)(wsrc + 4);

        __syncthreads();  // previous tile's math done
        As[kh * 8 + 0][mm] = a0.x; As[kh * 8 + 1][mm] = a0.y;
        As[kh * 8 + 2][mm] = a0.z; As[kh * 8 + 3][mm] = a0.w;
        As[kh * 8 + 4][mm] = a1.x; As[kh * 8 + 5][mm] = a1.y;
        As[kh * 8 + 6][mm] = a1.z; As[kh * 8 + 7][mm] = a1.w;
        *(float4*)&Bs[bk][bn] = b0;
        *(float4*)&Bs[bk][bn + 4] = b1;
        __syncthreads();

#pragma unroll
        for (int kk = 0; kk < 16; kk++) {
            float4 af0 = *(const float4*)&As[kk][tr * 8];
            float4 af1 = *(const float4*)&As[kk][tr * 8 + 4];
            ulonglong2 bu0 = *(const ulonglong2*)&Bs[kk][tc * 8];
            ulonglong2 bu1 = *(const ulonglong2*)&Bs[kk][tc * 8 + 4];
            unsigned long long bb[4] = {bu0.x, bu0.y, bu1.x, bu1.y};
            float af[8] = {af0.x, af0.y, af0.z, af0.w, af1.x, af1.y, af1.z, af1.w};
#pragma unroll
            for (int i = 0; i < 8; i++) {
                unsigned long long ai = splat2(af[i]);
#pragma unroll
                for (int j = 0; j < 4; j++) ffma2(acc[i][j], ai, bb[j]);
            }
        }
    }
#pragma unroll
    for (int i = 0; i < 8; i++) {
        int mo = m0 + tr * 8 + i;
        float o[8];
#pragma unroll
        for (int j = 0; j < 4; j++) {
            float2 f = unpack2(acc[i][j]);
            o[2 * j] = f.x;
            o[2 * j + 1] = f.y;
        }
#pragma unroll
        for (int jj = 0; jj < 8; jj++) {
            float v = o[jj] + bias[n0 + tc * 8 + jj];
            out[mo * 256 + n0 + tc * 8 + jj] = fmaxf(v, 0.f);
        }
    }
}

// ---------------- K3: maxpool 2x2 on conv2 output ----------------
__global__ void k_pool2(const float* __restrict__ in, float* __restrict__ out) {
    int idx = blockIdx.x * blockDim.x + threadIdx.x;
    if (idx >= 256 * 7 * 7 * 256) return;
    int c = idx & 255;
    int r = idx >> 8;
    int px = r % 7; r /= 7;
    int py = r % 7;
    int b = r / 7;
    float m = -1e30f;
#pragma unroll
    for (int dy = 0; dy < 2; dy++)
#pragma unroll
        for (int dx = 0; dx < 2; dx++)
            m = fmaxf(m, in[((b * 14 + 2 * py + dy) * 14 + 2 * px + dx) * 256 + c]);
    out[idx] = m;
}

// ---------------- K4: encoder FC, split-K partials. grid (16 kchunk, 4 btile) ----
__global__ __launch_bounds__(256) void k_enc_part(const float* __restrict__ h2,
                                                  const float* __restrict__ ew) {
    int kc = blockIdx.x;
    int b0 = blockIdx.y * 64;
    __shared__ float As[8][64];
    __shared__ float Bs[8][64];
    int t = threadIdx.x;
    int abb = t >> 2, akk = (t & 3) * 2;
    int bkk = t >> 5, bll = (t & 31) * 2;
    int tr = t >> 4, tc = t & 15;
    float acc[4][4] = {};
    int kbase = kc * 784;
    for (int ks = 0; ks < 784; ks += 8) {
        int k0 = kbase + ks;
        float2 av = *(const float2*)&h2[(b0 + abb) * 12544 + k0 + akk];
        float2 bv = *(const float2*)&ew[(k0 + bkk) * 64 + bll];
        __syncthreads();
        As[akk][abb] = av.x;
        As[akk + 1][abb] = av.y;
        *(float2*)&Bs[bkk][bll] = bv;
        __syncthreads();
#pragma unroll
        for (int kk = 0; kk < 8; kk++) {
            float a[4], b[4];
#pragma unroll
            for (int i = 0; i < 4; i++) a[i] = As[kk][tr * 4 + i];
#pragma unroll
            for (int j = 0; j < 4; j++) b[j] = Bs[kk][tc * 4 + j];
#pragma unroll
            for (int i = 0; i < 4; i++)
#pragma unroll
                for (int j = 0; j < 4; j++) acc[i][j] += a[i] * b[j];
        }
    }
#pragma unroll
    for (int i = 0; i < 4; i++)
#pragma unroll
        for (int j = 0; j < 4; j++)
            g_encp[(kc * 256 + b0 + tr * 4 + i) * 64 + tc * 4 + j] = acc[i][j];
}

__global__ void k_enc_reduce(const float* __restrict__ eb) {
    int idx = blockIdx.x * 256 + threadIdx.x;
    if (idx >= 256 * 64) return;
    float s = eb[idx & 63];
#pragma unroll
    for (int kc = 0; kc < 16; kc++) s += g_encp[kc * 16384 + idx];
    g_z[idx] = s;  // z_e rows 0..255
}

// ---------------- K5: distances + argmin (first-min tiebreak) + gather z_q --------
__global__ __launch_bounds__(256) void k_argmin(const float* __restrict__ emb) {
    int b = blockIdx.x;
    __shared__ float zb[64];
    __shared__ float ds[256];
    __shared__ int ki[256];
    int t = threadIdx.x;
    if (t < 64) zb[t] = g_z[b * 64 + t];
    __syncthreads();
    float d = 0.f;
    const float* e = emb + t * 64;
#pragma unroll 8
    for (int j = 0; j < 64; j++) {
        float df = zb[j] - e[j];
        d += df * df;
    }
    ds[t] = d;
    ki[t] = t;
    __syncthreads();
    for (int s = 128; s > 0; s >>= 1) {
        if (t < s) {
            float d2 = ds[t + s];
            int k2 = ki[t + s];
            if (d2 < ds[t] || (d2 == ds[t] && k2 < ki[t])) { ds[t] = d2; ki[t] = k2; }
        }
        __syncthreads();
    }
    int kb = ki[0];
    if (t < 64) g_z[(256 + b) * 64 + t] = emb[kb * 64 + t];  // z_q rows 256..511
}

// ---------------- K6: decoder FC for both z_e and z_q. grid (98 ntile, 8 mtile) ---
__global__ __launch_bounds__(256) void k_decfc(const float* __restrict__ dw,
                                               const float* __restrict__ db) {
    int n0 = blockIdx.x * 128;
    int m0 = blockIdx.y * 64;
    __shared__ float Zs[64][64];  // [k][row]
    __shared__ float Bs[32][128];
    int t = threadIdx.x;
    {
        int rr = t >> 2, kk0 = (t & 3) * 16;
        const float* zp = &g_z[(m0 + rr) * 64 + kk0];
#pragma unroll
        for (int q = 0; q < 4; q++) {
            float4 v = *(const float4*)(zp + q * 4);
            Zs[kk0 + q * 4 + 0][rr] = v.x; Zs[kk0 + q * 4 + 1][rr] = v.y;
            Zs[kk0 + q * 4 + 2][rr] = v.z; Zs[kk0 + q * 4 + 3][rr] = v.w;
        }
    }
    int tr = t >> 5;
    int tc = t & 31;
    float acc[8][4] = {};
    for (int khf = 0; khf < 2; khf++) {
        __syncthreads();
        {
            int nn = (t & 31) * 4;
            int kk = t >> 5;
#pragma unroll
            for (int q = 0; q < 4; q++) {
                int row = kk + q * 8;
                *(float4*)&Bs[row][nn] =
                    *(const float4*)&dw[(khf * 32 + row) * 12544 + n0 + nn];
            }
        }
        __syncthreads();
#pragma unroll
        for (int kk = 0; kk < 32; kk++) {
            int kg = khf * 32 + kk;
            float a[8];
#pragma unroll
            for (int i = 0; i < 8; i++) a[i] = Zs[kg][tr * 8 + i];
            float4 b4 = *(const float4*)&Bs[kk][tc * 4];
            float bb[4] = {b4.x, b4.y, b4.z, b4.w};
#pragma unroll
            for (int i = 0; i < 8; i++)
#pragma unroll
                for (int j = 0; j < 4; j++) acc[i][j] += a[i] * bb[j];
        }
    }
#pragma unroll
    for (int i = 0; i < 8; i++) {
        int m = m0 + tr * 8 + i;
#pragma unroll
        for (int j = 0; j < 4; j++) {
            int f = n0 + tc * 4 + j;
            g_d[m * 12544 + f] = acc[i][j] + db[f];
        }
    }
}

// ---------------- K8: deconv2 (upsample fold) + sigmoid. grid (512 img, 2 half) ---
__global__ __launch_bounds__(256) void k_deconv2(const float* __restrict__ w2,
                                                 const float* __restrict__ b2,
                                                 float* __restrict__ out) {
    int img = blockIdx.x;
    int half = blockIdx.y;
    int y0 = half * 14;
    int gbase = half * 6;
    __shared__ float gs[8][14][64];
    __shared__ float ws[16][64];
    __shared__ float pacc[392];
    int t = threadIdx.x;
    int wrp = t >> 5, lane = t & 31;
    pacc[t] = 0.f;
    if (t < 136) pacc[256 + t] = 0.f;
    float bias = b2[0];
    for (int cc = 0; cc < 4; cc++) {
        __syncthreads();
        for (int e = t; e < 8 * 14 * 64; e += 256) {
            int c = e & 63, xx = (e >> 6) % 14, r = e / 896;
            gs[r][xx][c] = g_g1[((img * 14 + gbase + r) * 14 + xx) * 256 + cc * 64 + c];
        }
        for (int e = t; e < 1024; e += 256) {
            int c = e & 63, tap = e >> 6;
            ws[tap][c] = w2[tap * 256 + cc * 64 + c];
        }
        __syncthreads();
        for (int p = wrp; p < 392; p += 8) {
            int yy = p / 28, x = p % 28;
            int y = y0 + yy;
            float r = 0.f;
#pragma unroll
            for (int ky = 0; ky < 4; ky++) {
                int uy = y - 1 + ky;
                if ((unsigned)uy >= 28u) continue;
                int gy = (uy >> 1) - gbase;
#pragma unroll
                for (int kx = 0; kx < 4; kx++) {
                    int ux = x - 1 + kx;
                    if ((unsigned)ux >= 28u) continue;
                    int gx = ux >> 1;
                    const float* gp = &gs[gy][gx][0];
                    const float* wp = &ws[ky * 4 + kx][0];
                    r += gp[lane] * wp[lane] + gp[lane + 32] * wp[lane + 32];
                }
            }
#pragma unroll
            for (int s = 16; s > 0; s >>= 1) r += __shfl_xor_sync(0xffffffffu, r, s);
            if (lane == 0) pacc[p] += r;
        }
    }
    __syncthreads();
    for (int p = t; p < 392; p += 256) {
        int yy = p / 28, x = p % 28;
        float v = pacc[p] + bias;
        out[img * 784 + (y0 + yy) * 28 + x] = 1.f / (1.f + expf(-v));
    }
}

// ---------------- launch ----------------
extern "C" void kernel_launch(void* const* d_in, const int* in_sizes, int n_in,
                              void* d_out, int out_size) {
    const float* x   = (const float*)d_in[0];
    const float* c1w = (const float*)d_in[1];
    const float* c1b = (const float*)d_in[2];
    const float* c2w = (const float*)d_in[3];
    const float* c2b = (const float*)d_in[4];
    const float* ew  = (const float*)d_in[5];
    const float* eb  = (const float*)d_in[6];
    const float* emb = (const float*)d_in[7];
    const float* dw  = (const float*)d_in[8];
    const float* db  = (const float*)d_in[9];
    const float* d1w = (const float*)d_in[10];
    const float* d1b = (const float*)d_in[11];
    const float* d2w = (const float*)d_in[12];
    const float* d2b = (const float*)d_in[13];
    float* out = (float*)d_out;

    void *p_h1, *p_c2, *p_h2, *p_d, *p_g1;
    cudaGetSymbolAddress(&p_h1, g_h1);
    cudaGetSymbolAddress(&p_c2, g_c2);
    cudaGetSymbolAddress(&p_h2, g_h2);
    cudaGetSymbolAddress(&p_d, g_d);
    cudaGetSymbolAddress(&p_g1, g_g1);

    k_conv1pool<<<dim3(14, 256), 256>>>(x, c1w, c1b);
    k_convgemm<0><<<dim3(392, 2), 256>>>((const float*)p_h1, c2w, c2b, (float*)p_c2);
    k_pool2<<<(256 * 7 * 7 * 256 + 255) / 256, 256>>>((const float*)p_c2, (float*)p_h2);
    k_enc_part<<<dim3(16, 4), 256>>>((const float*)p_h2, ew);
    k_enc_reduce<<<64, 256>>>(eb);
    k_argmin<<<256, 256>>>(emb);
    k_decfc<<<dim3(98, 8), 256>>>(dw, db);
    k_convgemm<1><<<dim3(784, 2), 256>>>((const float*)p_d, d1w, d1b, (float*)p_g1);
    k_deconv2<<<dim3(512, 2), 256>>>(d2w, d2b, out);
}

// round 3
// speedup vs baseline: 2.1736x; 2.1736x over previous
#include <cuda_runtime.h>
#include <cuda_bf16.h>
#include <math.h>
#include <stdint.h>

// ============================ helpers ============================
__device__ __forceinline__ uint32_t smem_to_u32(const void* p) {
    uint32_t a;
    asm("{ .reg .u64 t; cvta.to.shared.u64 t, %1; cvt.u32.u64 %0, t; }"
        : "=r"(a) : "l"(p));
    return a;
}
__device__ __forceinline__ void cp_async16(uint32_t smem, const void* g, uint32_t sz) {
    asm volatile("cp.async.cg.shared.global [%0], [%1], 16, %2;"
                 :: "r"(smem), "l"(g), "r"(sz) : "memory");
}
#define CP_COMMIT() asm volatile("cp.async.commit_group;" ::: "memory")
#define CP_WAIT1() asm volatile("cp.async.wait_group 1;" ::: "memory")
#define CP_WAIT0() asm volatile("cp.async.wait_group 0;" ::: "memory")
#define LDSM4(r0, r1, r2, r3, addr) \
    asm volatile("ldmatrix.sync.aligned.m8n8.x4.shared.b16 {%0,%1,%2,%3}, [%4];" \
                 : "=r"(r0), "=r"(r1), "=r"(r2), "=r"(r3) : "r"(addr))
__device__ __forceinline__ void mma16816(float* c, const uint32_t* a, uint32_t b0,
                                         uint32_t b1) {
    asm volatile(
        "mma.sync.aligned.m16n8k16.row.col.f32.bf16.bf16.f32 "
        "{%0,%1,%2,%3}, {%4,%5,%6,%7}, {%8,%9}, {%0,%1,%2,%3};"
        : "+f"(c[0]), "+f"(c[1]), "+f"(c[2]), "+f"(c[3])
        : "r"(a[0]), "r"(a[1]), "r"(a[2]), "r"(a[3]), "r"(b0), "r"(b1));
}
#define SWZ(x) ((x) ^ (((x) >> 3) & 0x70))

// ============================ scratch (device globals) ============================
__device__ __align__(16) __nv_bfloat16 g_a1h[12845056];   // conv2 A limbs [pos][ch]
__device__ __align__(16) __nv_bfloat16 g_a1l[12845056];
__device__ __align__(16) __nv_bfloat16 g_a1l2[12845056];
__device__ __align__(16) __nv_bfloat16 g_w2h[1048576];    // conv2 B limbs [n][k]
__device__ __align__(16) __nv_bfloat16 g_w2l[1048576];
__device__ __align__(16) __nv_bfloat16 g_w2l2[1048576];
__device__ __align__(16) __nv_bfloat16 g_dh[6422528];     // deconv1 A limbs [pos][ch]
__device__ __align__(16) __nv_bfloat16 g_dl[6422528];
__device__ __align__(16) __nv_bfloat16 g_w1h[1048576];    // deconv1 B limbs [n][k]
__device__ __align__(16) __nv_bfloat16 g_w1l[1048576];
__device__ float g_c2[12845056];     // conv2 out (pre-pool)
__device__ float g_h2[3211264];      // pooled
__device__ float g_encp[262144];     // encoder split-K partials
__device__ float g_z[32768];         // rows 0..255 z_e, 256..511 z_q
__device__ float g_g1[25690112];     // deconv1 out

// ---------------- K1: conv1 + ReLU + maxpool -> 3 bf16 limb planes ----------------
__global__ __launch_bounds__(256) void k_conv1pool(const float* __restrict__ x,
                                                   const float* __restrict__ w1,
                                                   const float* __restrict__ b1) {
    int py = blockIdx.x;
    int b = blockIdx.y;
    int c = threadIdx.x;
    __shared__ float xs[5][32];
    for (int e = threadIdx.x; e < 5 * 32; e += 256) {
        int r = e / 32, cc = e % 32;
        int iy = 2 * py - 1 + r;
        int ix = cc - 1;
        float v = 0.f;
        if (iy >= 0 && iy < 28 && ix >= 0 && ix < 28) v = x[(b * 28 + iy) * 28 + ix];
        xs[r][cc] = v;
    }
    float w[16];
#pragma unroll
    for (int i = 0; i < 16; i++) w[i] = w1[i * 256 + c];
    float bias = b1[c];
    __syncthreads();
    for (int px = 0; px < 14; px++) {
        float mv = -1e30f;
#pragma unroll
        for (int dy = 0; dy < 2; dy++)
#pragma unroll
            for (int dx = 0; dx < 2; dx++) {
                float v = bias;
#pragma unroll
                for (int ky = 0; ky < 4; ky++)
#pragma unroll
                    for (int kx = 0; kx < 4; kx++)
                        v += xs[dy + ky][2 * px + dx + kx] * w[ky * 4 + kx];
                mv = fmaxf(mv, v);
            }
        float val = fmaxf(mv, 0.f);
        int idx = ((b * 14 + py) * 14 + px) * 256 + c;
        __nv_bfloat16 h = __float2bfloat16(val);
        float r1 = val - __bfloat162float(h);
        __nv_bfloat16 l = __float2bfloat16(r1);
        float r2 = r1 - __bfloat162float(l);
        g_a1h[idx] = h;
        g_a1l[idx] = l;
        g_a1l2[idx] = __float2bfloat16(r2);
    }
}

// ---------------- weight transpose + limb split: w[k][256] -> planes[n][4096] ----
template <int NL>
__global__ __launch_bounds__(256) void k_wsplit(const float* __restrict__ w,
                                                __nv_bfloat16* __restrict__ o0,
                                                __nv_bfloat16* __restrict__ o1,
                                                __nv_bfloat16* __restrict__ o2) {
    __shared__ float tile[32][33];
    int k0 = blockIdx.x * 32, n0 = blockIdx.y * 32;
    int tx = threadIdx.x & 31, ty = threadIdx.x >> 5;
#pragma unroll
    for (int r = 0; r < 32; r += 8) tile[ty + r][tx] = w[(k0 + ty + r) * 256 + n0 + tx];
    __syncthreads();
#pragma unroll
    for (int r = 0; r < 32; r += 8) {
        float v = tile[tx][ty + r];
        int n = n0 + ty + r;
        int idx = n * 4096 + k0 + tx;
        __nv_bfloat16 h = __float2bfloat16(v);
        o0[idx] = h;
        float r1 = v - __bfloat162float(h);
        __nv_bfloat16 l = __float2bfloat16(r1);
        o1[idx] = l;
        if (NL == 3) o2[idx] = __float2bfloat16(r1 - __bfloat162float(l));
    }
}

// ============== HMMA implicit-GEMM conv (M=128, N=128 per CTA, K=4096) ============
// UPS=0: A from 14x14 grid (conv2). UPS=1: A from 7x7 grid, upsample folded.
// Multi-limb: pairs packed in PACK, 4 bits each: la | (lb<<2).
template <int UPS, int NLA, int NLB, int NP, unsigned PACK>
__global__ __launch_bounds__(256, 1) void k_hmma(
    const __nv_bfloat16* __restrict__ a0p, const __nv_bfloat16* __restrict__ a1p,
    const __nv_bfloat16* __restrict__ a2p, const __nv_bfloat16* __restrict__ b0p,
    const __nv_bfloat16* __restrict__ b1p, const __nv_bfloat16* __restrict__ b2p,
    const float* __restrict__ bias, float* __restrict__ out) {
    constexpr int STAGE = (NLA + NLB) * 16384;  // bytes per k64 stage
    extern __shared__ __align__(1024) char smem[];
    const uint32_t sb = smem_to_u32(smem);
    const int t = threadIdx.x;
    const int wid = t >> 5;
    const int lane = t & 31;
    const int wr = wid & 1;    // M half (64 rows)
    const int wc = wid >> 1;   // N quarter (32 cols)
    const int m0 = blockIdx.x * 128;
    const int n0 = blockIdx.y * 128;

    const __nv_bfloat16* ap[3] = {a0p, a1p, a2p};
    const __nv_bfloat16* bp[3] = {b0p, b1p, b2p};

    // ---- loader geometry: rows r_j = (t>>3)+32j, 16B seg = t&7 ----
    const int rr = t >> 3;
    const int seg = t & 7;
    int imgA[4], oyA[4], oxA[4];
    uint32_t stsO[4];
#pragma unroll
    for (int j = 0; j < 4; j++) {
        int m = m0 + rr + 32 * j;
        imgA[j] = m / 196;
        int p = m % 196;
        oyA[j] = p / 14;
        oxA[j] = p % 14;
        stsO[j] = SWZ((uint32_t)((rr + 32 * j) * 128 + seg * 16));
    }

    float acc[4][4][4];
#pragma unroll
    for (int i = 0; i < 4; i++)
#pragma unroll
        for (int j = 0; j < 4; j++)
#pragma unroll
            for (int q = 0; q < 4; q++) acc[i][j][q] = 0.f;

    // ---- ldmatrix per-thread address components ----
    // A: row = wr*64 + mt*16 + (lane&15); byte col = kk*32 + (lane>>4)*16
    const int arow = wr * 64 + (lane & 15);
    const uint32_t acolbase = (uint32_t)((lane >> 4) * 16);
    // B: n = wc*32 + nt2*16 + (lane&7) + (lane>>4)*8; khalf = (lane>>3)&1
    const int brow = wc * 32 + (lane & 7) + (lane >> 4) * 8;
    const uint32_t bcolbase = (uint32_t)(((lane >> 3) & 1) * 16);

    // ---- stage issue ----
    auto issue = [&](int s, int buf) {
        const int tap = s >> 2;
        const int ky = tap >> 2, kx = tap & 3;
        const int ch0 = (s & 3) * 64;
        const uint32_t sbuf = sb + (uint32_t)buf * STAGE;
#pragma unroll
        for (int j = 0; j < 4; j++) {
            int iy = oyA[j] - 1 + ky;
            int ix = oxA[j] - 1 + kx;
            bool v = ((unsigned)iy < 14u) && ((unsigned)ix < 14u);
            int pos;
            if (UPS)
                pos = imgA[j] * 49 + (iy >> 1) * 7 + (ix >> 1);
            else
                pos = imgA[j] * 196 + iy * 14 + ix;
            int aoff = v ? (pos * 256 + ch0 + seg * 8) : 0;
            uint32_t sz = v ? 16u : 0u;
#pragma unroll
            for (int la = 0; la < NLA; la++)
                cp_async16(sbuf + la * 16384 + stsO[j], ap[la] + aoff, sz);
            size_t boff = (size_t)(n0 + rr + 32 * j) * 4096 + s * 64 + seg * 8;
#pragma unroll
            for (int lb = 0; lb < NLB; lb++)
                cp_async16(sbuf + (NLA + lb) * 16384 + stsO[j], bp[lb] + boff, 16u);
        }
    };

    issue(0, 0);
    CP_COMMIT();

    for (int s = 0; s < 64; s++) {
        if (s < 63) {
            issue(s + 1, (s + 1) & 1);
            CP_COMMIT();
            CP_WAIT1();
        } else {
            CP_WAIT0();
        }
        __syncthreads();

        const uint32_t abase = sb + (uint32_t)(s & 1) * STAGE;
        const uint32_t bbase = abase + NLA * 16384;
#pragma unroll
        for (int kk = 0; kk < 4; kk++) {
            uint32_t af[NLA][4][4];
            uint32_t bf[NLB][2][4];
            const uint32_t acol = acolbase + kk * 32;
#pragma unroll
            for (int la = 0; la < NLA; la++)
#pragma unroll
                for (int mt = 0; mt < 4; mt++) {
                    int row = arow + mt * 16;
                    uint32_t addr =
                        abase + la * 16384 + row * 128 + (acol ^ ((row & 7) * 16));
                    LDSM4(af[la][mt][0], af[la][mt][1], af[la][mt][2], af[la][mt][3],
                          addr);
                }
            const uint32_t bcol = bcolbase + kk * 32;
#pragma unroll
            for (int lb = 0; lb < NLB; lb++)
#pragma unroll
                for (int nt2 = 0; nt2 < 2; nt2++) {
                    int row = brow + nt2 * 16;
                    uint32_t addr =
                        bbase + lb * 16384 + row * 128 + (bcol ^ ((row & 7) * 16));
                    LDSM4(bf[lb][nt2][0], bf[lb][nt2][1], bf[lb][nt2][2],
                          bf[lb][nt2][3], addr);
                }
#pragma unroll
            for (int p = 0; p < NP; p++) {
                constexpr unsigned PK = PACK;
                const int code = (int)((PK >> (4 * p)) & 15u);
                const int la = code & 3;
                const int lb = code >> 2;
#pragma unroll
                for (int mt = 0; mt < 4; mt++)
#pragma unroll
                    for (int nt = 0; nt < 4; nt++)
                        mma16816(acc[mt][nt], af[la][mt],
                                 bf[lb][nt >> 1][(nt & 1) * 2],
                                 bf[lb][nt >> 1][(nt & 1) * 2 + 1]);
            }
        }
        __syncthreads();
    }

    // ---- epilogue: bias + ReLU, fp32 out [m][256] ----
#pragma unroll
    for (int mt = 0; mt < 4; mt++) {
#pragma unroll
        for (int nt = 0; nt < 4; nt++) {
            int row = m0 + wr * 64 + mt * 16 + (lane >> 2);
            int col = n0 + wc * 32 + nt * 8 + (lane & 3) * 2;
            float b0v = bias[col], b1v = bias[col + 1];
            float2 v0, v1;
            v0.x = fmaxf(acc[mt][nt][0] + b0v, 0.f);
            v0.y = fmaxf(acc[mt][nt][1] + b1v, 0.f);
            v1.x = fmaxf(acc[mt][nt][2] + b0v, 0.f);
            v1.y = fmaxf(acc[mt][nt][3] + b1v, 0.f);
            *(float2*)(out + (size_t)row * 256 + col) = v0;
            *(float2*)(out + (size_t)(row + 8) * 256 + col) = v1;
        }
    }
}

// ---------------- K3: maxpool 2x2 on conv2 output ----------------
__global__ void k_pool2(const float* __restrict__ in, float* __restrict__ out) {
    int idx = blockIdx.x * blockDim.x + threadIdx.x;
    if (idx >= 256 * 7 * 7 * 256) return;
    int c = idx & 255;
    int r = idx >> 8;
    int px = r % 7; r /= 7;
    int py = r % 7;
    int b = r / 7;
    float m = -1e30f;
#pragma unroll
    for (int dy = 0; dy < 2; dy++)
#pragma unroll
        for (int dx = 0; dx < 2; dx++)
            m = fmaxf(m, in[((b * 14 + 2 * py + dy) * 14 + 2 * px + dx) * 256 + c]);
    out[idx] = m;
}

// ---------------- K4: encoder FC split-K ----------------
__global__ __launch_bounds__(256) void k_enc_part(const float* __restrict__ h2,
                                                  const float* __restrict__ ew) {
    int kc = blockIdx.x;
    int b0 = blockIdx.y * 64;
    __shared__ float As[8][64];
    __shared__ float Bs[8][64];
    int t = threadIdx.x;
    int abb = t >> 2, akk = (t & 3) * 2;
    int bkk = t >> 5, bll = (t & 31) * 2;
    int tr = t >> 4, tc = t & 15;
    float acc[4][4] = {};
    int kbase = kc * 784;
    for (int ks = 0; ks < 784; ks += 8) {
        int k0 = kbase + ks;
        float2 av = *(const float2*)&h2[(b0 + abb) * 12544 + k0 + akk];
        float2 bv = *(const float2*)&ew[(k0 + bkk) * 64 + bll];
        __syncthreads();
        As[akk][abb] = av.x;
        As[akk + 1][abb] = av.y;
        *(float2*)&Bs[bkk][bll] = bv;
        __syncthreads();
#pragma unroll
        for (int kk = 0; kk < 8; kk++) {
            float a[4], b[4];
#pragma unroll
            for (int i = 0; i < 4; i++) a[i] = As[kk][tr * 4 + i];
#pragma unroll
            for (int j = 0; j < 4; j++) b[j] = Bs[kk][tc * 4 + j];
#pragma unroll
            for (int i = 0; i < 4; i++)
#pragma unroll
                for (int j = 0; j < 4; j++) acc[i][j] += a[i] * b[j];
        }
    }
#pragma unroll
    for (int i = 0; i < 4; i++)
#pragma unroll
        for (int j = 0; j < 4; j++)
            g_encp[(kc * 256 + b0 + tr * 4 + i) * 64 + tc * 4 + j] = acc[i][j];
}

__global__ void k_enc_reduce(const float* __restrict__ eb) {
    int idx = blockIdx.x * 256 + threadIdx.x;
    if (idx >= 256 * 64) return;
    float s = eb[idx & 63];
#pragma unroll
    for (int kc = 0; kc < 16; kc++) s += g_encp[kc * 16384 + idx];
    g_z[idx] = s;
}

// ---------------- K5: argmin + gather z_q ----------------
__global__ __launch_bounds__(256) void k_argmin(const float* __restrict__ emb) {
    int b = blockIdx.x;
    __shared__ float zb[64];
    __shared__ float ds[256];
    __shared__ int ki[256];
    int t = threadIdx.x;
    if (t < 64) zb[t] = g_z[b * 64 + t];
    __syncthreads();
    float d = 0.f;
    const float* e = emb + t * 64;
#pragma unroll 8
    for (int j = 0; j < 64; j++) {
        float df = zb[j] - e[j];
        d += df * df;
    }
    ds[t] = d;
    ki[t] = t;
    __syncthreads();
    for (int s = 128; s > 0; s >>= 1) {
        if (t < s) {
            float d2 = ds[t + s];
            int k2 = ki[t + s];
            if (d2 < ds[t] || (d2 == ds[t] && k2 < ki[t])) { ds[t] = d2; ki[t] = k2; }
        }
        __syncthreads();
    }
    int kb = ki[0];
    if (t < 64) g_z[(256 + b) * 64 + t] = emb[kb * 64 + t];
}

// ---------------- K6: decoder FC -> 2 bf16 limb planes ----------------
__global__ __launch_bounds__(256) void k_decfc(const float* __restrict__ dw,
                                               const float* __restrict__ db) {
    int n0 = blockIdx.x * 128;
    int m0 = blockIdx.y * 64;
    __shared__ float Zs[64][64];
    __shared__ float Bs[32][128];
    int t = threadIdx.x;
    {
        int rr = t >> 2, kk0 = (t & 3) * 16;
        const float* zp = &g_z[(m0 + rr) * 64 + kk0];
#pragma unroll
        for (int q = 0; q < 4; q++) {
            float4 v = *(const float4*)(zp + q * 4);
            Zs[kk0 + q * 4 + 0][rr] = v.x; Zs[kk0 + q * 4 + 1][rr] = v.y;
            Zs[kk0 + q * 4 + 2][rr] = v.z; Zs[kk0 + q * 4 + 3][rr] = v.w;
        }
    }
    int tr = t >> 5;
    int tc = t & 31;
    float acc[8][4] = {};
    for (int khf = 0; khf < 2; khf++) {
        __syncthreads();
        {
            int nn = (t & 31) * 4;
            int kk = t >> 5;
#pragma unroll
            for (int q = 0; q < 4; q++) {
                int row = kk + q * 8;
                *(float4*)&Bs[row][nn] =
                    *(const float4*)&dw[(khf * 32 + row) * 12544 + n0 + nn];
            }
        }
        __syncthreads();
#pragma unroll
        for (int kk = 0; kk < 32; kk++) {
            int kg = khf * 32 + kk;
            float a[8];
#pragma unroll
            for (int i = 0; i < 8; i++) a[i] = Zs[kg][tr * 8 + i];
            float4 b4 = *(const float4*)&Bs[kk][tc * 4];
            float bb[4] = {b4.x, b4.y, b4.z, b4.w};
#pragma unroll
            for (int i = 0; i < 8; i++)
#pragma unroll
                for (int j = 0; j < 4; j++) acc[i][j] += a[i] * bb[j];
        }
    }
#pragma unroll
    for (int i = 0; i < 8; i++) {
        int m = m0 + tr * 8 + i;
#pragma unroll
        for (int j = 0; j < 4; j++) {
            int f = n0 + tc * 4 + j;
            float v = acc[i][j] + db[f];
            size_t idx = (size_t)m * 12544 + f;
            __nv_bfloat16 h = __float2bfloat16(v);
            g_dh[idx] = h;
            g_dl[idx] = __float2bfloat16(v - __bfloat162float(h));
        }
    }
}

// ---------------- K8: deconv2 + sigmoid ----------------
__global__ __launch_bounds__(256) void k_deconv2(const float* __restrict__ w2,
                                                 const float* __restrict__ b2,
                                                 float* __restrict__ out) {
    int img = blockIdx.x;
    int half = blockIdx.y;
    int y0 = half * 14;
    int gbase = half * 6;
    __shared__ float gs[8][14][64];
    __shared__ float ws[16][64];
    __shared__ float pacc[392];
    int t = threadIdx.x;
    int wrp = t >> 5, lane = t & 31;
    pacc[t] = 0.f;
    if (t < 136) pacc[256 + t] = 0.f;
    float bias = b2[0];
    for (int cc = 0; cc < 4; cc++) {
        __syncthreads();
        for (int e = t; e < 8 * 14 * 64; e += 256) {
            int c = e & 63, xx = (e >> 6) % 14, r = e / 896;
            gs[r][xx][c] = g_g1[((img * 14 + gbase + r) * 14 + xx) * 256 + cc * 64 + c];
        }
        for (int e = t; e < 1024; e += 256) {
            int c = e & 63, tap = e >> 6;
            ws[tap][c] = w2[tap * 256 + cc * 64 + c];
        }
        __syncthreads();
        for (int p = wrp; p < 392; p += 8) {
            int yy = p / 28, x = p % 28;
            int y = y0 + yy;
            float r = 0.f;
#pragma unroll
            for (int ky = 0; ky < 4; ky++) {
                int uy = y - 1 + ky;
                if ((unsigned)uy >= 28u) continue;
                int gy = (uy >> 1) - gbase;
#pragma unroll
                for (int kx = 0; kx < 4; kx++) {
                    int ux = x - 1 + kx;
                    if ((unsigned)ux >= 28u) continue;
                    int gx = ux >> 1;
                    const float* gp = &gs[gy][gx][0];
                    const float* wp = &ws[ky * 4 + kx][0];
                    r += gp[lane] * wp[lane] + gp[lane + 32] * wp[lane + 32];
                }
            }
#pragma unroll
            for (int s = 16; s > 0; s >>= 1) r += __shfl_xor_sync(0xffffffffu, r, s);
            if (lane == 0) pacc[p] += r;
        }
    }
    __syncthreads();
    for (int p = t; p < 392; p += 256) {
        int yy = p / 28, x = p % 28;
        float v = pacc[p] + bias;
        out[img * 784 + (y0 + yy) * 28 + x] = 1.f / (1.f + expf(-v));
    }
}

// ---------------- launch ----------------
static constexpr unsigned PACK_ENC = 0x825140u;  // (0,0)(0,1)(1,0)(1,1)(2,0)(0,2)
static constexpr unsigned PACK_DEC = 0x140u;     // (0,0)(0,1)(1,0)
static constexpr int SMEM_ENC = 2 * 6 * 16384;   // 196608
static constexpr int SMEM_DEC = 2 * 4 * 16384;   // 131072

extern "C" void kernel_launch(void* const* d_in, const int* in_sizes, int n_in,
                              void* d_out, int out_size) {
    const float* x   = (const float*)d_in[0];
    const float* c1w = (const float*)d_in[1];
    const float* c1b = (const float*)d_in[2];
    const float* c2w = (const float*)d_in[3];
    const float* c2b = (const float*)d_in[4];
    const float* ew  = (const float*)d_in[5];
    const float* eb  = (const float*)d_in[6];
    const float* emb = (const float*)d_in[7];
    const float* dw  = (const float*)d_in[8];
    const float* db  = (const float*)d_in[9];
    const float* d1w = (const float*)d_in[10];
    const float* d1b = (const float*)d_in[11];
    const float* d2w = (const float*)d_in[12];
    const float* d2b = (const float*)d_in[13];
    float* out = (float*)d_out;

    void *pa1h, *pa1l, *pa1l2, *pw2h, *pw2l, *pw2l2;
    void *pdh, *pdl, *pw1h, *pw1l, *pc2, *ph2, *pg1;
    cudaGetSymbolAddress(&pa1h, g_a1h);
    cudaGetSymbolAddress(&pa1l, g_a1l);
    cudaGetSymbolAddress(&pa1l2, g_a1l2);
    cudaGetSymbolAddress(&pw2h, g_w2h);
    cudaGetSymbolAddress(&pw2l, g_w2l);
    cudaGetSymbolAddress(&pw2l2, g_w2l2);
    cudaGetSymbolAddress(&pdh, g_dh);
    cudaGetSymbolAddress(&pdl, g_dl);
    cudaGetSymbolAddress(&pw1h, g_w1h);
    cudaGetSymbolAddress(&pw1l, g_w1l);
    cudaGetSymbolAddress(&pc2, g_c2);
    cudaGetSymbolAddress(&ph2, g_h2);
    cudaGetSymbolAddress(&pg1, g_g1);

    cudaFuncSetAttribute((const void*)k_hmma<0, 3, 3, 6, PACK_ENC>,
                         cudaFuncAttributeMaxDynamicSharedMemorySize, SMEM_ENC);
    cudaFuncSetAttribute((const void*)k_hmma<1, 2, 2, 3, PACK_DEC>,
                         cudaFuncAttributeMaxDynamicSharedMemorySize, SMEM_DEC);

    k_conv1pool<<<dim3(14, 256), 256>>>(x, c1w, c1b);
    k_wsplit<3><<<dim3(128, 8), 256>>>(c2w, (__nv_bfloat16*)pw2h,
                                       (__nv_bfloat16*)pw2l, (__nv_bfloat16*)pw2l2);
    k_wsplit<2><<<dim3(128, 8), 256>>>(d1w, (__nv_bfloat16*)pw1h,
                                       (__nv_bfloat16*)pw1l, (__nv_bfloat16*)pw1l);
    k_hmma<0, 3, 3, 6, PACK_ENC><<<dim3(392, 2), 256, SMEM_ENC>>>(
        (const __nv_bfloat16*)pa1h, (const __nv_bfloat16*)pa1l,
        (const __nv_bfloat16*)pa1l2, (const __nv_bfloat16*)pw2h,
        (const __nv_bfloat16*)pw2l, (const __nv_bfloat16*)pw2l2, c2b, (float*)pc2);
    k_pool2<<<(256 * 7 * 7 * 256 + 255) / 256, 256>>>((const float*)pc2, (float*)ph2);
    k_enc_part<<<dim3(16, 4), 256>>>((const float*)ph2, ew);
    k_enc_reduce<<<64, 256>>>(eb);
    k_argmin<<<256, 256>>>(emb);
    k_decfc<<<dim3(98, 8), 256>>>(dw, db);
    k_hmma<1, 2, 2, 3, PACK_DEC><<<dim3(784, 2), 256, SMEM_DEC>>>(
        (const __nv_bfloat16*)pdh, (const __nv_bfloat16*)pdl,
        (const __nv_bfloat16*)pdl, (const __nv_bfloat16*)pw1h,
        (const __nv_bfloat16*)pw1l, (const __nv_bfloat16*)pw1l, d1b, (float*)pg1);
    k_deconv2<<<dim3(512, 2), 256>>>(d2w, d2b, out);
}

// round 4
// speedup vs baseline: 3.4582x; 1.5910x over previous
#include <cuda_runtime.h>
#include <cuda_fp16.h>
#include <math.h>
#include <stdint.h>

// ============================ helpers ============================
__device__ __forceinline__ uint32_t smem_to_u32(const void* p) {
    uint32_t a;
    asm("{ .reg .u64 t; cvta.to.shared.u64 t, %1; cvt.u32.u64 %0, t; }"
        : "=r"(a) : "l"(p));
    return a;
}
__device__ __forceinline__ void cp_async16(uint32_t smem, const void* g, uint32_t sz) {
    asm volatile("cp.async.cg.shared.global [%0], [%1], 16, %2;"
                 :: "r"(smem), "l"(g), "r"(sz) : "memory");
}
#define CP_COMMIT() asm volatile("cp.async.commit_group;" ::: "memory")
#define CP_WAIT1() asm volatile("cp.async.wait_group 1;" ::: "memory")
#define CP_WAIT0() asm volatile("cp.async.wait_group 0;" ::: "memory")
#define LDSM4(r0, r1, r2, r3, addr) \
    asm volatile("ldmatrix.sync.aligned.m8n8.x4.shared.b16 {%0,%1,%2,%3}, [%4];" \
                 : "=r"(r0), "=r"(r1), "=r"(r2), "=r"(r3) : "r"(addr))
__device__ __forceinline__ void mma16816(float* c, const uint32_t* a, uint32_t b0,
                                         uint32_t b1) {
    asm volatile(
        "mma.sync.aligned.m16n8k16.row.col.f32.f16.f16.f32 "
        "{%0,%1,%2,%3}, {%4,%5,%6,%7}, {%8,%9}, {%0,%1,%2,%3};"
        : "+f"(c[0]), "+f"(c[1]), "+f"(c[2]), "+f"(c[3])
        : "r"(a[0]), "r"(a[1]), "r"(a[2]), "r"(a[3]), "r"(b0), "r"(b1));
}
#define SWZ(x) ((x) ^ (((x) >> 3) & 0x70))

// ============================ scratch (device globals) ============================
__device__ __align__(16) __half g_a1h[12845056];   // conv2 A limbs [pos][ch]
__device__ __align__(16) __half g_a1l[12845056];
__device__ __align__(16) __half g_w2h[1048576];    // conv2 B limbs [n][4096]
__device__ __align__(16) __half g_w2l[1048576];
__device__ __align__(16) __half g_dh[6422528];     // deconv1 A limbs [pos][ch]
__device__ __align__(16) __half g_dl[6422528];
__device__ __align__(16) __half g_w1h[1638400];    // deconv1 parity weights
__device__ __align__(16) __half g_w1l[1638400];
__device__ float g_c2[12845056];     // conv2 out (pre-pool)
__device__ float g_h2[3211264];      // pooled
__device__ float g_encp[262144];     // encoder split-K partials
__device__ float g_z[32768];         // rows 0..255 z_e, 256..511 z_q
__device__ float g_g1[25690112];     // deconv1 out

// ---------------- K1: conv1 + ReLU + maxpool -> 2 fp16 limb planes ----------------
__global__ __launch_bounds__(256) void k_conv1pool(const float* __restrict__ x,
                                                   const float* __restrict__ w1,
                                                   const float* __restrict__ b1) {
    int py = blockIdx.x;
    int b = blockIdx.y;
    int c = threadIdx.x;
    __shared__ float xs[5][32];
    for (int e = threadIdx.x; e < 5 * 32; e += 256) {
        int r = e / 32, cc = e % 32;
        int iy = 2 * py - 1 + r;
        int ix = cc - 1;
        float v = 0.f;
        if (iy >= 0 && iy < 28 && ix >= 0 && ix < 28) v = x[(b * 28 + iy) * 28 + ix];
        xs[r][cc] = v;
    }
    float w[16];
#pragma unroll
    for (int i = 0; i < 16; i++) w[i] = w1[i * 256 + c];
    float bias = b1[c];
    __syncthreads();
    for (int px = 0; px < 14; px++) {
        float mv = -1e30f;
#pragma unroll
        for (int dy = 0; dy < 2; dy++)
#pragma unroll
            for (int dx = 0; dx < 2; dx++) {
                float v = bias;
#pragma unroll
                for (int ky = 0; ky < 4; ky++)
#pragma unroll
                    for (int kx = 0; kx < 4; kx++)
                        v += xs[dy + ky][2 * px + dx + kx] * w[ky * 4 + kx];
                mv = fmaxf(mv, v);
            }
        float val = fmaxf(mv, 0.f);
        int idx = ((b * 14 + py) * 14 + px) * 256 + c;
        __half h = __float2half(val);
        g_a1h[idx] = h;
        g_a1l[idx] = __float2half(val - __half2float(h));
    }
}

// ---------------- conv2 weight transpose + fp16 limb split ----------------
__global__ __launch_bounds__(256) void k_wsplit2(const float* __restrict__ w,
                                                 __half* __restrict__ o0,
                                                 __half* __restrict__ o1) {
    __shared__ float tile[32][33];
    int k0 = blockIdx.x * 32, n0 = blockIdx.y * 32;
    int tx = threadIdx.x & 31, ty = threadIdx.x >> 5;
#pragma unroll
    for (int r = 0; r < 32; r += 8) tile[ty + r][tx] = w[(k0 + ty + r) * 256 + n0 + tx];
    __syncthreads();
#pragma unroll
    for (int r = 0; r < 32; r += 8) {
        float v = tile[tx][ty + r];
        int n = n0 + ty + r;
        int idx = n * 4096 + k0 + tx;
        __half h = __float2half(v);
        o0[idx] = h;
        o1[idx] = __float2half(v - __half2float(h));
    }
}

// ---------------- deconv1 parity weight combine: 4 classes ----------------
// class c: py=c>>1, px=c&1; TY=3-py, TX=3-px, Kc=TY*TX*256
// layout: plane[woff(c) + n*Kc + (ty*TX+tx)*256 + cin]
__global__ void k_wcomb(const float* __restrict__ w, __half* __restrict__ oh,
                        __half* __restrict__ ol) {
    int idx = blockIdx.x * 256 + threadIdx.x;
    if (idx >= 1638400) return;
    int c, base;
    if (idx < 589824) { c = 0; base = 0; }
    else if (idx < 983040) { c = 1; base = 589824; }
    else if (idx < 1376256) { c = 2; base = 983040; }
    else { c = 3; base = 1376256; }
    int py = c >> 1, px = c & 1;
    int TX = 3 - px;
    int Kc = (3 - py) * TX * 256;
    int rem = idx - base;
    int n = rem / Kc;
    int k = rem % Kc;
    int tap = k >> 8, cin = k & 255;
    int ty = tap / TX, tx = tap % TX;
    int kys, kyn, kxs, kxn;
    if (py == 0) { kys = (ty == 0) ? 0 : (ty == 1) ? 1 : 3; kyn = (ty == 1) ? 2 : 1; }
    else { kys = ty * 2; kyn = 2; }
    if (px == 0) { kxs = (tx == 0) ? 0 : (tx == 1) ? 1 : 3; kxn = (tx == 1) ? 2 : 1; }
    else { kxs = tx * 2; kxn = 2; }
    float s = 0.f;
    for (int a = 0; a < kyn; a++)
        for (int b = 0; b < kxn; b++)
            s += w[(((kys + a) * 4 + kxs + b) * 256 + cin) * 256 + n];
    __half h = __float2half(s);
    oh[idx] = h;
    ol[idx] = __float2half(s - __half2float(h));
}

// ============== encoder HMMA implicit-GEMM conv2 (M=128,N=128,K=4096) =============
// fp16 2-limb x 2-limb, 4 passes (full product)
__global__ __launch_bounds__(256, 1) void k_hmma_enc(
    const __half* __restrict__ a0p, const __half* __restrict__ a1p,
    const __half* __restrict__ b0p, const __half* __restrict__ b1p,
    const float* __restrict__ bias, float* __restrict__ out) {
    constexpr int STAGE = 65536;
    extern __shared__ __align__(1024) char smem[];
    const uint32_t sb = smem_to_u32(smem);
    const int t = threadIdx.x;
    const int wid = t >> 5;
    const int lane = t & 31;
    const int wr = wid & 1;
    const int wc = wid >> 1;
    const int m0 = blockIdx.x * 128;
    const int n0 = blockIdx.y * 128;

    const int rr = t >> 3;
    const int seg = t & 7;
    int imgA[4], oyA[4], oxA[4];
    uint32_t stsO[4];
#pragma unroll
    for (int j = 0; j < 4; j++) {
        int m = m0 + rr + 32 * j;
        imgA[j] = m / 196;
        int p = m % 196;
        oyA[j] = p / 14;
        oxA[j] = p % 14;
        stsO[j] = SWZ((uint32_t)((rr + 32 * j) * 128 + seg * 16));
    }

    float acc[4][4][4];
#pragma unroll
    for (int i = 0; i < 4; i++)
#pragma unroll
        for (int j = 0; j < 4; j++)
#pragma unroll
            for (int q = 0; q < 4; q++) acc[i][j][q] = 0.f;

    const int arow = wr * 64 + (lane & 15);
    const uint32_t acolbase = (uint32_t)((lane >> 4) * 16);
    const int brow = wc * 32 + (lane & 7) + (lane >> 4) * 8;
    const uint32_t bcolbase = (uint32_t)(((lane >> 3) & 1) * 16);

    auto issue = [&](int s, int buf) {
        const int tap = s >> 2;
        const int ky = tap >> 2, kx = tap & 3;
        const int ch0 = (s & 3) * 64;
        const uint32_t sbuf = sb + (uint32_t)buf * STAGE;
#pragma unroll
        for (int j = 0; j < 4; j++) {
            int iy = oyA[j] - 1 + ky;
            int ix = oxA[j] - 1 + kx;
            bool v = ((unsigned)iy < 14u) && ((unsigned)ix < 14u);
            int pos = imgA[j] * 196 + iy * 14 + ix;
            int aoff = v ? (pos * 256 + ch0 + seg * 8) : 0;
            uint32_t sz = v ? 16u : 0u;
            cp_async16(sbuf + stsO[j], a0p + aoff, sz);
            cp_async16(sbuf + 16384 + stsO[j], a1p + aoff, sz);
            size_t boff = (size_t)(n0 + rr + 32 * j) * 4096 + s * 64 + seg * 8;
            cp_async16(sbuf + 32768 + stsO[j], b0p + boff, 16u);
            cp_async16(sbuf + 49152 + stsO[j], b1p + boff, 16u);
        }
    };

    issue(0, 0);
    CP_COMMIT();

    for (int s = 0; s < 64; s++) {
        if (s < 63) {
            issue(s + 1, (s + 1) & 1);
            CP_COMMIT();
            CP_WAIT1();
        } else {
            CP_WAIT0();
        }
        __syncthreads();

        const uint32_t abase = sb + (uint32_t)(s & 1) * STAGE;
        const uint32_t bbase = abase + 32768;
#pragma unroll
        for (int kk = 0; kk < 4; kk++) {
            uint32_t af[2][4][4];
            uint32_t bf[2][2][4];
            const uint32_t acol = acolbase + kk * 32;
#pragma unroll
            for (int la = 0; la < 2; la++)
#pragma unroll
                for (int mt = 0; mt < 4; mt++) {
                    int row = arow + mt * 16;
                    uint32_t addr =
                        abase + la * 16384 + row * 128 + (acol ^ ((row & 7) * 16));
                    LDSM4(af[la][mt][0], af[la][mt][1], af[la][mt][2], af[la][mt][3],
                          addr);
                }
            const uint32_t bcol = bcolbase + kk * 32;
#pragma unroll
            for (int lb = 0; lb < 2; lb++)
#pragma unroll
                for (int nt2 = 0; nt2 < 2; nt2++) {
                    int row = brow + nt2 * 16;
                    uint32_t addr =
                        bbase + lb * 16384 + row * 128 + (bcol ^ ((row & 7) * 16));
                    LDSM4(bf[lb][nt2][0], bf[lb][nt2][1], bf[lb][nt2][2],
                          bf[lb][nt2][3], addr);
                }
#pragma unroll
            for (int la = 0; la < 2; la++)
#pragma unroll
                for (int lb = 0; lb < 2; lb++)
#pragma unroll
                    for (int mt = 0; mt < 4; mt++)
#pragma unroll
                        for (int nt = 0; nt < 4; nt++)
                            mma16816(acc[mt][nt], af[la][mt],
                                     bf[lb][nt >> 1][(nt & 1) * 2],
                                     bf[lb][nt >> 1][(nt & 1) * 2 + 1]);
        }
        __syncthreads();
    }

#pragma unroll
    for (int mt = 0; mt < 4; mt++) {
#pragma unroll
        for (int nt = 0; nt < 4; nt++) {
            int row = m0 + wr * 64 + mt * 16 + (lane >> 2);
            int col = n0 + wc * 32 + nt * 8 + (lane & 3) * 2;
            float b0v = bias[col], b1v = bias[col + 1];
            float2 v0, v1;
            v0.x = fmaxf(acc[mt][nt][0] + b0v, 0.f);
            v0.y = fmaxf(acc[mt][nt][1] + b1v, 0.f);
            v1.x = fmaxf(acc[mt][nt][2] + b0v, 0.f);
            v1.y = fmaxf(acc[mt][nt][3] + b1v, 0.f);
            *(float2*)(out + (size_t)row * 256 + col) = v0;
            *(float2*)(out + (size_t)(row + 8) * 256 + col) = v1;
        }
    }
}

// ============== decoder HMMA: parity classes, K in {2304,1536,1536,1024} ==========
// fp16 2-limb x 2-limb, 3 passes (hh, hl, lh)
__global__ __launch_bounds__(256, 1) void k_hmma_dec(
    const __half* __restrict__ a0p, const __half* __restrict__ a1p,
    const __half* __restrict__ b0p, const __half* __restrict__ b1p,
    const float* __restrict__ bias, float* __restrict__ out) {
    constexpr int STAGE = 65536;
    extern __shared__ __align__(1024) char smem[];
    const uint32_t sb = smem_to_u32(smem);
    const int t = threadIdx.x;
    const int wid = t >> 5;
    const int lane = t & 31;
    const int wr = wid & 1;
    const int wc = wid >> 1;
    const int m0 = blockIdx.x * 128;
    const int n0 = blockIdx.y * 128;
    const int cls = blockIdx.z;
    const int py = cls >> 1, px = cls & 1;
    const int TX = 3 - px;
    const int TY = 3 - py;
    const int nst = TY * TX * 4;
    const int Kc = TY * TX * 256;
    const int woff = (cls == 0) ? 0 : (cls == 1) ? 589824 : (cls == 2) ? 983040
                                                                       : 1376256;

    const int rr = t >> 3;
    const int seg = t & 7;
    int imgA[4], syA[4], sxA[4];
    uint32_t stsO[4];
#pragma unroll
    for (int j = 0; j < 4; j++) {
        int m = m0 + rr + 32 * j;
        imgA[j] = m / 49;
        int p = m % 49;
        syA[j] = p / 7;
        sxA[j] = p % 7;
        stsO[j] = SWZ((uint32_t)((rr + 32 * j) * 128 + seg * 16));
    }

    float acc[4][4][4];
#pragma unroll
    for (int i = 0; i < 4; i++)
#pragma unroll
        for (int j = 0; j < 4; j++)
#pragma unroll
            for (int q = 0; q < 4; q++) acc[i][j][q] = 0.f;

    const int arow = wr * 64 + (lane & 15);
    const uint32_t acolbase = (uint32_t)((lane >> 4) * 16);
    const int brow = wc * 32 + (lane & 7) + (lane >> 4) * 8;
    const uint32_t bcolbase = (uint32_t)(((lane >> 3) & 1) * 16);

    auto issue = [&](int s, int buf) {
        const int tap = s >> 2;
        const int ch0 = (s & 3) * 64;
        const int ty = tap / TX, tx = tap % TX;
        const uint32_t sbuf = sb + (uint32_t)buf * STAGE;
#pragma unroll
        for (int j = 0; j < 4; j++) {
            int iy = syA[j] + ty + (py - 1);
            int ix = sxA[j] + tx + (px - 1);
            bool v = ((unsigned)iy < 7u) && ((unsigned)ix < 7u);
            int pos = imgA[j] * 49 + iy * 7 + ix;
            int aoff = v ? (pos * 256 + ch0 + seg * 8) : 0;
            uint32_t sz = v ? 16u : 0u;
            cp_async16(sbuf + stsO[j], a0p + aoff, sz);
            cp_async16(sbuf + 16384 + stsO[j], a1p + aoff, sz);
            size_t boff = (size_t)woff + (size_t)(n0 + rr + 32 * j) * Kc + s * 64 +
                          seg * 8;
            cp_async16(sbuf + 32768 + stsO[j], b0p + boff, 16u);
            cp_async16(sbuf + 49152 + stsO[j], b1p + boff, 16u);
        }
    };

    issue(0, 0);
    CP_COMMIT();

    for (int s = 0; s < nst; s++) {
        if (s + 1 < nst) {
            issue(s + 1, (s + 1) & 1);
            CP_COMMIT();
            CP_WAIT1();
        } else {
            CP_WAIT0();
        }
        __syncthreads();

        const uint32_t abase = sb + (uint32_t)(s & 1) * STAGE;
        const uint32_t bbase = abase + 32768;
#pragma unroll
        for (int kk = 0; kk < 4; kk++) {
            uint32_t af[2][4][4];
            uint32_t bf[2][2][4];
            const uint32_t acol = acolbase + kk * 32;
#pragma unroll
            for (int la = 0; la < 2; la++)
#pragma unroll
                for (int mt = 0; mt < 4; mt++) {
                    int row = arow + mt * 16;
                    uint32_t addr =
                        abase + la * 16384 + row * 128 + (acol ^ ((row & 7) * 16));
                    LDSM4(af[la][mt][0], af[la][mt][1], af[la][mt][2], af[la][mt][3],
                          addr);
                }
            const uint32_t bcol = bcolbase + kk * 32;
#pragma unroll
            for (int lb = 0; lb < 2; lb++)
#pragma unroll
                for (int nt2 = 0; nt2 < 2; nt2++) {
                    int row = brow + nt2 * 16;
                    uint32_t addr =
                        bbase + lb * 16384 + row * 128 + (bcol ^ ((row & 7) * 16));
                    LDSM4(bf[lb][nt2][0], bf[lb][nt2][1], bf[lb][nt2][2],
                          bf[lb][nt2][3], addr);
                }
#pragma unroll
            for (int p = 0; p < 3; p++) {
                const int la = (p == 2) ? 1 : 0;
                const int lb = (p == 1) ? 1 : 0;
#pragma unroll
                for (int mt = 0; mt < 4; mt++)
#pragma unroll
                    for (int nt = 0; nt < 4; nt++)
                        mma16816(acc[mt][nt], af[la][mt],
                                 bf[lb][nt >> 1][(nt & 1) * 2],
                                 bf[lb][nt >> 1][(nt & 1) * 2 + 1]);
            }
        }
        __syncthreads();
    }

    // epilogue: scatter rows back to the 14x14 grid, bias + ReLU
#pragma unroll
    for (int mt = 0; mt < 4; mt++) {
#pragma unroll
        for (int nt = 0; nt < 4; nt++) {
            int col = n0 + wc * 32 + nt * 8 + (lane & 3) * 2;
            float b0v = bias[col], b1v = bias[col + 1];
#pragma unroll
            for (int half8 = 0; half8 < 2; half8++) {
                int m = m0 + wr * 64 + mt * 16 + (lane >> 2) + half8 * 8;
                int img = m / 49;
                int p = m % 49;
                int oy = 2 * (p / 7) + py;
                int ox = 2 * (p % 7) + px;
                float2 v;
                v.x = fmaxf(acc[mt][nt][half8 * 2] + b0v, 0.f);
                v.y = fmaxf(acc[mt][nt][half8 * 2 + 1] + b1v, 0.f);
                *(float2*)(out + (size_t)((img * 14 + oy) * 14 + ox) * 256 + col) = v;
            }
        }
    }
}

// ---------------- K3: maxpool 2x2 on conv2 output ----------------
__global__ void k_pool2(const float* __restrict__ in, float* __restrict__ out) {
    int idx = blockIdx.x * blockDim.x + threadIdx.x;
    if (idx >= 256 * 7 * 7 * 256) return;
    int c = idx & 255;
    int r = idx >> 8;
    int px = r % 7; r /= 7;
    int py = r % 7;
    int b = r / 7;
    float m = -1e30f;
#pragma unroll
    for (int dy = 0; dy < 2; dy++)
#pragma unroll
        for (int dx = 0; dx < 2; dx++)
            m = fmaxf(m, in[((b * 14 + 2 * py + dy) * 14 + 2 * px + dx) * 256 + c]);
    out[idx] = m;
}

// ---------------- K4: encoder FC split-K ----------------
__global__ __launch_bounds__(256) void k_enc_part(const float* __restrict__ h2,
                                                  const float* __restrict__ ew) {
    int kc = blockIdx.x;
    int b0 = blockIdx.y * 64;
    __shared__ float As[8][64];
    __shared__ float Bs[8][64];
    int t = threadIdx.x;
    int abb = t >> 2, akk = (t & 3) * 2;
    int bkk = t >> 5, bll = (t & 31) * 2;
    int tr = t >> 4, tc = t & 15;
    float acc[4][4] = {};
    int kbase = kc * 784;
    for (int ks = 0; ks < 784; ks += 8) {
        int k0 = kbase + ks;
        float2 av = *(const float2*)&h2[(b0 + abb) * 12544 + k0 + akk];
        float2 bv = *(const float2*)&ew[(k0 + bkk) * 64 + bll];
        __syncthreads();
        As[akk][abb] = av.x;
        As[akk + 1][abb] = av.y;
        *(float2*)&Bs[bkk][bll] = bv;
        __syncthreads();
#pragma unroll
        for (int kk = 0; kk < 8; kk++) {
            float a[4], b[4];
#pragma unroll
            for (int i = 0; i < 4; i++) a[i] = As[kk][tr * 4 + i];
#pragma unroll
            for (int j = 0; j < 4; j++) b[j] = Bs[kk][tc * 4 + j];
#pragma unroll
            for (int i = 0; i < 4; i++)
#pragma unroll
                for (int j = 0; j < 4; j++) acc[i][j] += a[i] * b[j];
        }
    }
#pragma unroll
    for (int i = 0; i < 4; i++)
#pragma unroll
        for (int j = 0; j < 4; j++)
            g_encp[(kc * 256 + b0 + tr * 4 + i) * 64 + tc * 4 + j] = acc[i][j];
}

__global__ void k_enc_reduce(const float* __restrict__ eb) {
    int idx = blockIdx.x * 256 + threadIdx.x;
    if (idx >= 256 * 64) return;
    float s = eb[idx & 63];
#pragma unroll
    for (int kc = 0; kc < 16; kc++) s += g_encp[kc * 16384 + idx];
    g_z[idx] = s;
}

// ---------------- K5: argmin + gather z_q ----------------
__global__ __launch_bounds__(256) void k_argmin(const float* __restrict__ emb) {
    int b = blockIdx.x;
    __shared__ float zb[64];
    __shared__ float ds[256];
    __shared__ int ki[256];
    int t = threadIdx.x;
    if (t < 64) zb[t] = g_z[b * 64 + t];
    __syncthreads();
    float d = 0.f;
    const float* e = emb + t * 64;
#pragma unroll 8
    for (int j = 0; j < 64; j++) {
        float df = zb[j] - e[j];
        d += df * df;
    }
    ds[t] = d;
    ki[t] = t;
    __syncthreads();
    for (int s = 128; s > 0; s >>= 1) {
        if (t < s) {
            float d2 = ds[t + s];
            int k2 = ki[t + s];
            if (d2 < ds[t] || (d2 == ds[t] && k2 < ki[t])) { ds[t] = d2; ki[t] = k2; }
        }
        __syncthreads();
    }
    int kb = ki[0];
    if (t < 64) g_z[(256 + b) * 64 + t] = emb[kb * 64 + t];
}

// ---------------- K6: decoder FC -> 2 fp16 limb planes ----------------
__global__ __launch_bounds__(256) void k_decfc(const float* __restrict__ dw,
                                               const float* __restrict__ db) {
    int n0 = blockIdx.x * 128;
    int m0 = blockIdx.y * 64;
    __shared__ float Zs[64][64];
    __shared__ float Bs[32][128];
    int t = threadIdx.x;
    {
        int rr = t >> 2, kk0 = (t & 3) * 16;
        const float* zp = &g_z[(m0 + rr) * 64 + kk0];
#pragma unroll
        for (int q = 0; q < 4; q++) {
            float4 v = *(const float4*)(zp + q * 4);
            Zs[kk0 + q * 4 + 0][rr] = v.x; Zs[kk0 + q * 4 + 1][rr] = v.y;
            Zs[kk0 + q * 4 + 2][rr] = v.z; Zs[kk0 + q * 4 + 3][rr] = v.w;
        }
    }
    int tr = t >> 5;
    int tc = t & 31;
    float acc[8][4] = {};
    for (int khf = 0; khf < 2; khf++) {
        __syncthreads();
        {
            int nn = (t & 31) * 4;
            int kk = t >> 5;
#pragma unroll
            for (int q = 0; q < 4; q++) {
                int row = kk + q * 8;
                *(float4*)&Bs[row][nn] =
                    *(const float4*)&dw[(khf * 32 + row) * 12544 + n0 + nn];
            }
        }
        __syncthreads();
#pragma unroll
        for (int kk = 0; kk < 32; kk++) {
            int kg = khf * 32 + kk;
            float a[8];
#pragma unroll
            for (int i = 0; i < 8; i++) a[i] = Zs[kg][tr * 8 + i];
            float4 b4 = *(const float4*)&Bs[kk][tc * 4];
            float bb[4] = {b4.x, b4.y, b4.z, b4.w};
#pragma unroll
            for (int i = 0; i < 8; i++)
#pragma unroll
                for (int j = 0; j < 4; j++) acc[i][j] += a[i] * bb[j];
        }
    }
#pragma unroll
    for (int i = 0; i < 8; i++) {
        int m = m0 + tr * 8 + i;
#pragma unroll
        for (int j = 0; j < 4; j++) {
            int f = n0 + tc * 4 + j;
            float v = acc[i][j] + db[f];
            size_t idx = (size_t)m * 12544 + f;
            __half h = __float2half(v);
            g_dh[idx] = h;
            g_dl[idx] = __float2half(v - __half2float(h));
        }
    }
}

// ---------------- K8: deconv2 + sigmoid ----------------
__global__ __launch_bounds__(256) void k_deconv2(const float* __restrict__ w2,
                                                 const float* __restrict__ b2,
                                                 float* __restrict__ out) {
    int img = blockIdx.x;
    int half = blockIdx.y;
    int y0 = half * 14;
    int gbase = half * 6;
    __shared__ float gs[8][14][64];
    __shared__ float ws[16][64];
    __shared__ float pacc[392];
    int t = threadIdx.x;
    int wrp = t >> 5, lane = t & 31;
    pacc[t] = 0.f;
    if (t < 136) pacc[256 + t] = 0.f;
    float bias = b2[0];
    for (int cc = 0; cc < 4; cc++) {
        __syncthreads();
        for (int e = t; e < 8 * 14 * 64; e += 256) {
            int c = e & 63, xx = (e >> 6) % 14, r = e / 896;
            gs[r][xx][c] = g_g1[((img * 14 + gbase + r) * 14 + xx) * 256 + cc * 64 + c];
        }
        for (int e = t; e < 1024; e += 256) {
            int c = e & 63, tap = e >> 6;
            ws[tap][c] = w2[tap * 256 + cc * 64 + c];
        }
        __syncthreads();
        for (int p = wrp; p < 392; p += 8) {
            int yy = p / 28, x = p % 28;
            int y = y0 + yy;
            float r = 0.f;
#pragma unroll
            for (int ky = 0; ky < 4; ky++) {
                int uy = y - 1 + ky;
                if ((unsigned)uy >= 28u) continue;
                int gy = (uy >> 1) - gbase;
#pragma unroll
                for (int kx = 0; kx < 4; kx++) {
                    int ux = x - 1 + kx;
                    if ((unsigned)ux >= 28u) continue;
                    int gx = ux >> 1;
                    const float* gp = &gs[gy][gx][0];
                    const float* wp = &ws[ky * 4 + kx][0];
                    r += gp[lane] * wp[lane] + gp[lane + 32] * wp[lane + 32];
                }
            }
#pragma unroll
            for (int s = 16; s > 0; s >>= 1) r += __shfl_xor_sync(0xffffffffu, r, s);
            if (lane == 0) pacc[p] += r;
        }
    }
    __syncthreads();
    for (int p = t; p < 392; p += 256) {
        int yy = p / 28, x = p % 28;
        float v = pacc[p] + bias;
        out[img * 784 + (y0 + yy) * 28 + x] = 1.f / (1.f + expf(-v));
    }
}

// ---------------- launch ----------------
static constexpr int SMEM_HMMA = 2 * 65536;  // 131072

extern "C" void kernel_launch(void* const* d_in, const int* in_sizes, int n_in,
                              void* d_out, int out_size) {
    const float* x   = (const float*)d_in[0];
    const float* c1w = (const float*)d_in[1];
    const float* c1b = (const float*)d_in[2];
    const float* c2w = (const float*)d_in[3];
    const float* c2b = (const float*)d_in[4];
    const float* ew  = (const float*)d_in[5];
    const float* eb  = (const float*)d_in[6];
    const float* emb = (const float*)d_in[7];
    const float* dw  = (const float*)d_in[8];
    const float* db  = (const float*)d_in[9];
    const float* d1w = (const float*)d_in[10];
    const float* d1b = (const float*)d_in[11];
    const float* d2w = (const float*)d_in[12];
    const float* d2b = (const float*)d_in[13];
    float* out = (float*)d_out;

    void *pa1h, *pa1l, *pw2h, *pw2l, *pdh, *pdl, *pw1h, *pw1l, *pc2, *ph2, *pg1;
    cudaGetSymbolAddress(&pa1h, g_a1h);
    cudaGetSymbolAddress(&pa1l, g_a1l);
    cudaGetSymbolAddress(&pw2h, g_w2h);
    cudaGetSymbolAddress(&pw2l, g_w2l);
    cudaGetSymbolAddress(&pdh, g_dh);
    cudaGetSymbolAddress(&pdl, g_dl);
    cudaGetSymbolAddress(&pw1h, g_w1h);
    cudaGetSymbolAddress(&pw1l, g_w1l);
    cudaGetSymbolAddress(&pc2, g_c2);
    cudaGetSymbolAddress(&ph2, g_h2);
    cudaGetSymbolAddress(&pg1, g_g1);

    cudaFuncSetAttribute((const void*)k_hmma_enc,
                         cudaFuncAttributeMaxDynamicSharedMemorySize, SMEM_HMMA);
    cudaFuncSetAttribute((const void*)k_hmma_dec,
                         cudaFuncAttributeMaxDynamicSharedMemorySize, SMEM_HMMA);

    k_conv1pool<<<dim3(14, 256), 256>>>(x, c1w, c1b);
    k_wsplit2<<<dim3(128, 8), 256>>>(c2w, (__half*)pw2h, (__half*)pw2l);
    k_wcomb<<<(1638400 + 255) / 256, 256>>>(d1w, (__half*)pw1h, (__half*)pw1l);
    k_hmma_enc<<<dim3(392, 2), 256, SMEM_HMMA>>>(
        (const __half*)pa1h, (const __half*)pa1l, (const __half*)pw2h,
        (const __half*)pw2l, c2b, (float*)pc2);
    k_pool2<<<(256 * 7 * 7 * 256 + 255) / 256, 256>>>((const float*)pc2, (float*)ph2);
    k_enc_part<<<dim3(16, 4), 256>>>((const float*)ph2, ew);
    k_enc_reduce<<<64, 256>>>(eb);
    k_argmin<<<256, 256>>>(emb);
    k_decfc<<<dim3(98, 8), 256>>>(dw, db);
    k_hmma_dec<<<dim3(196, 2, 4), 256, SMEM_HMMA>>>(
        (const __half*)pdh, (const __half*)pdl, (const __half*)pw1h,
        (const __half*)pw1l, d1b, (float*)pg1);
    k_deconv2<<<dim3(512, 2), 256>>>(d2w, d2b, out);
}

// round 5
// speedup vs baseline: 3.8246x; 1.1059x over previous
#include <cuda_runtime.h>
#include <cuda_fp16.h>
#include <math.h>
#include <stdint.h>

// ============================ helpers ============================
__device__ __forceinline__ uint32_t smem_to_u32(const void* p) {
    uint32_t a;
    asm("{ .reg .u64 t; cvta.to.shared.u64 t, %1; cvt.u32.u64 %0, t; }"
        : "=r"(a) : "l"(p));
    return a;
}
__device__ __forceinline__ void cp_async16(uint32_t smem, const void* g, uint32_t sz) {
    asm volatile("cp.async.cg.shared.global [%0], [%1], 16, %2;"
                 :: "r"(smem), "l"(g), "r"(sz) : "memory");
}
#define CP_COMMIT() asm volatile("cp.async.commit_group;" ::: "memory")
#define CP_WAIT2() asm volatile("cp.async.wait_group 2;" ::: "memory")
#define CP_WAIT1() asm volatile("cp.async.wait_group 1;" ::: "memory")
#define CP_WAIT0() asm volatile("cp.async.wait_group 0;" ::: "memory")
#define LDSM4(r0, r1, r2, r3, addr) \
    asm volatile("ldmatrix.sync.aligned.m8n8.x4.shared.b16 {%0,%1,%2,%3}, [%4];" \
                 : "=r"(r0), "=r"(r1), "=r"(r2), "=r"(r3) : "r"(addr))
__device__ __forceinline__ void mma16816(float* c, const uint32_t* a, uint32_t b0,
                                         uint32_t b1) {
    asm volatile(
        "mma.sync.aligned.m16n8k16.row.col.f32.f16.f16.f32 "
        "{%0,%1,%2,%3}, {%4,%5,%6,%7}, {%8,%9}, {%0,%1,%2,%3};"
        : "+f"(c[0]), "+f"(c[1]), "+f"(c[2]), "+f"(c[3])
        : "r"(a[0]), "r"(a[1]), "r"(a[2]), "r"(a[3]), "r"(b0), "r"(b1));
}
#define SWZ(x) ((x) ^ (((x) >> 3) & 0x70))

// ============================ scratch (device globals) ============================
__device__ __align__(16) __half g_a1h[12845056];   // conv2 A limbs [pos][ch]
__device__ __align__(16) __half g_a1l[12845056];
__device__ __align__(16) __half g_w2h[1048576];    // conv2 B limbs [n][4096]
__device__ __align__(16) __half g_w2l[1048576];
__device__ __align__(16) __half g_dh[6422528];     // deconv1 A limbs [pos][ch]
__device__ __align__(16) __half g_dl[6422528];
__device__ __align__(16) __half g_w1h[1638400];    // deconv1 parity weights
__device__ __align__(16) __half g_w1l[1638400];
__device__ float g_h2[3211264];      // pooled conv2 out (atomicMax target)
__device__ float g_encp[262144];     // encoder split-K partials
__device__ float g_z[32768];         // rows 0..255 z_e, 256..511 z_q
__device__ float g_g1[25690112];     // deconv1 out

// ---------------- K0: zero h2 (needed for atomicMax pooling) ----------------
__global__ void k_zero_h2() {
    int i = blockIdx.x * 256 + threadIdx.x;
    if (i < 802816) *(((uint4*)g_h2) + i) = make_uint4(0u, 0u, 0u, 0u);
}

// ---------------- K1: conv1 + ReLU + maxpool -> 2 fp16 limb planes ----------------
__global__ __launch_bounds__(256) void k_conv1pool(const float* __restrict__ x,
                                                   const float* __restrict__ w1,
                                                   const float* __restrict__ b1) {
    int py = blockIdx.x;
    int b = blockIdx.y;
    int c = threadIdx.x;
    __shared__ float xs[5][32];
    for (int e = threadIdx.x; e < 5 * 32; e += 256) {
        int r = e / 32, cc = e % 32;
        int iy = 2 * py - 1 + r;
        int ix = cc - 1;
        float v = 0.f;
        if (iy >= 0 && iy < 28 && ix >= 0 && ix < 28) v = x[(b * 28 + iy) * 28 + ix];
        xs[r][cc] = v;
    }
    float w[16];
#pragma unroll
    for (int i = 0; i < 16; i++) w[i] = w1[i * 256 + c];
    float bias = b1[c];
    __syncthreads();
    for (int px = 0; px < 14; px++) {
        float mv = -1e30f;
#pragma unroll
        for (int dy = 0; dy < 2; dy++)
#pragma unroll
            for (int dx = 0; dx < 2; dx++) {
                float v = bias;
#pragma unroll
                for (int ky = 0; ky < 4; ky++)
#pragma unroll
                    for (int kx = 0; kx < 4; kx++)
                        v += xs[dy + ky][2 * px + dx + kx] * w[ky * 4 + kx];
                mv = fmaxf(mv, v);
            }
        float val = fmaxf(mv, 0.f);
        int idx = ((b * 14 + py) * 14 + px) * 256 + c;
        __half h = __float2half(val);
        g_a1h[idx] = h;
        g_a1l[idx] = __float2half(val - __half2float(h));
    }
}

// ---------------- conv2 weight transpose + fp16 limb split ----------------
__global__ __launch_bounds__(256) void k_wsplit2(const float* __restrict__ w,
                                                 __half* __restrict__ o0,
                                                 __half* __restrict__ o1) {
    __shared__ float tile[32][33];
    int k0 = blockIdx.x * 32, n0 = blockIdx.y * 32;
    int tx = threadIdx.x & 31, ty = threadIdx.x >> 5;
#pragma unroll
    for (int r = 0; r < 32; r += 8) tile[ty + r][tx] = w[(k0 + ty + r) * 256 + n0 + tx];
    __syncthreads();
#pragma unroll
    for (int r = 0; r < 32; r += 8) {
        float v = tile[tx][ty + r];
        int n = n0 + ty + r;
        int idx = n * 4096 + k0 + tx;
        __half h = __float2half(v);
        o0[idx] = h;
        o1[idx] = __float2half(v - __half2float(h));
    }
}

// ---------------- deconv1 parity weight combine: 4 classes ----------------
__global__ void k_wcomb(const float* __restrict__ w, __half* __restrict__ oh,
                        __half* __restrict__ ol) {
    int idx = blockIdx.x * 256 + threadIdx.x;
    if (idx >= 1638400) return;
    int c, base;
    if (idx < 589824) { c = 0; base = 0; }
    else if (idx < 983040) { c = 1; base = 589824; }
    else if (idx < 1376256) { c = 2; base = 983040; }
    else { c = 3; base = 1376256; }
    int py = c >> 1, px = c & 1;
    int TX = 3 - px;
    int Kc = (3 - py) * TX * 256;
    int rem = idx - base;
    int n = rem / Kc;
    int k = rem % Kc;
    int tap = k >> 8, cin = k & 255;
    int ty = tap / TX, tx = tap % TX;
    int kys, kyn, kxs, kxn;
    if (py == 0) { kys = (ty == 0) ? 0 : (ty == 1) ? 1 : 3; kyn = (ty == 1) ? 2 : 1; }
    else { kys = ty * 2; kyn = 2; }
    if (px == 0) { kxs = (tx == 0) ? 0 : (tx == 1) ? 1 : 3; kxn = (tx == 1) ? 2 : 1; }
    else { kxs = tx * 2; kxn = 2; }
    float s = 0.f;
    for (int a = 0; a < kyn; a++)
        for (int b = 0; b < kxn; b++)
            s += w[(((kys + a) * 4 + kxs + b) * 256 + cin) * 256 + n];
    __half h = __float2half(s);
    oh[idx] = h;
    ol[idx] = __float2half(s - __half2float(h));
}

// ============== encoder HMMA implicit-GEMM conv2 (M=128,N=128,K=4096) =============
// fp16 2-limb, 3 passes (hh, hl, lh). Epilogue: bias+ReLU+2x2 maxpool via atomicMax.
__global__ __launch_bounds__(256, 1) void k_hmma_enc(
    const __half* __restrict__ a0p, const __half* __restrict__ a1p,
    const __half* __restrict__ b0p, const __half* __restrict__ b1p,
    const float* __restrict__ bias, float* __restrict__ outpool) {
    constexpr int STAGE = 65536;
    extern __shared__ __align__(1024) char smem[];
    const uint32_t sb = smem_to_u32(smem);
    const int t = threadIdx.x;
    const int wid = t >> 5;
    const int lane = t & 31;
    const int wr = wid & 1;
    const int wc = wid >> 1;
    const int m0 = blockIdx.x * 128;
    const int n0 = blockIdx.y * 128;

    const int rr = t >> 3;
    const int seg = t & 7;
    int imgA[4], oyA[4], oxA[4];
    uint32_t stsO[4];
#pragma unroll
    for (int j = 0; j < 4; j++) {
        int m = m0 + rr + 32 * j;
        imgA[j] = m / 196;
        int p = m % 196;
        oyA[j] = p / 14;
        oxA[j] = p % 14;
        stsO[j] = SWZ((uint32_t)((rr + 32 * j) * 128 + seg * 16));
    }

    float acc[4][4][4];
#pragma unroll
    for (int i = 0; i < 4; i++)
#pragma unroll
        for (int j = 0; j < 4; j++)
#pragma unroll
            for (int q = 0; q < 4; q++) acc[i][j][q] = 0.f;

    const int arow = wr * 64 + (lane & 15);
    const uint32_t acolbase = (uint32_t)((lane >> 4) * 16);
    const int brow = wc * 32 + (lane & 7) + (lane >> 4) * 8;
    const uint32_t bcolbase = (uint32_t)(((lane >> 3) & 1) * 16);

    auto issue = [&](int s, int buf) {
        const int tap = s >> 2;
        const int ky = tap >> 2, kx = tap & 3;
        const int ch0 = (s & 3) * 64;
        const uint32_t sbuf = sb + (uint32_t)buf * STAGE;
#pragma unroll
        for (int j = 0; j < 4; j++) {
            int iy = oyA[j] - 1 + ky;
            int ix = oxA[j] - 1 + kx;
            bool v = ((unsigned)iy < 14u) && ((unsigned)ix < 14u);
            int pos = imgA[j] * 196 + iy * 14 + ix;
            int aoff = v ? (pos * 256 + ch0 + seg * 8) : 0;
            uint32_t sz = v ? 16u : 0u;
            cp_async16(sbuf + stsO[j], a0p + aoff, sz);
            cp_async16(sbuf + 16384 + stsO[j], a1p + aoff, sz);
            size_t boff = (size_t)(n0 + rr + 32 * j) * 4096 + s * 64 + seg * 8;
            cp_async16(sbuf + 32768 + stsO[j], b0p + boff, 16u);
            cp_async16(sbuf + 49152 + stsO[j], b1p + boff, 16u);
        }
    };

    issue(0, 0);
    CP_COMMIT();
    issue(1, 1);
    CP_COMMIT();

    int buf = 0;
    for (int s = 0; s < 64; s++) {
        if (s + 2 < 64) {
            int nb = buf + 2;
            if (nb >= 3) nb -= 3;
            issue(s + 2, nb);
            CP_COMMIT();
            CP_WAIT2();
        } else if (s + 1 < 64) {
            CP_WAIT1();
        } else {
            CP_WAIT0();
        }
        __syncthreads();

        const uint32_t abase = sb + (uint32_t)buf * STAGE;
        const uint32_t bbase = abase + 32768;
#pragma unroll
        for (int kk = 0; kk < 4; kk++) {
            uint32_t af[2][4][4];
            uint32_t bf[2][2][4];
            const uint32_t acol = acolbase + kk * 32;
#pragma unroll
            for (int la = 0; la < 2; la++)
#pragma unroll
                for (int mt = 0; mt < 4; mt++) {
                    int row = arow + mt * 16;
                    uint32_t addr =
                        abase + la * 16384 + row * 128 + (acol ^ ((row & 7) * 16));
                    LDSM4(af[la][mt][0], af[la][mt][1], af[la][mt][2], af[la][mt][3],
                          addr);
                }
            const uint32_t bcol = bcolbase + kk * 32;
#pragma unroll
            for (int lb = 0; lb < 2; lb++)
#pragma unroll
                for (int nt2 = 0; nt2 < 2; nt2++) {
                    int row = brow + nt2 * 16;
                    uint32_t addr =
                        bbase + lb * 16384 + row * 128 + (bcol ^ ((row & 7) * 16));
                    LDSM4(bf[lb][nt2][0], bf[lb][nt2][1], bf[lb][nt2][2],
                          bf[lb][nt2][3], addr);
                }
#pragma unroll
            for (int p = 0; p < 3; p++) {
                const int la = (p == 2) ? 1 : 0;
                const int lb = (p == 1) ? 1 : 0;
#pragma unroll
                for (int mt = 0; mt < 4; mt++)
#pragma unroll
                    for (int nt = 0; nt < 4; nt++)
                        mma16816(acc[mt][nt], af[la][mt],
                                 bf[lb][nt >> 1][(nt & 1) * 2],
                                 bf[lb][nt >> 1][(nt & 1) * 2 + 1]);
            }
        }
        __syncthreads();
        if (++buf == 3) buf = 0;
    }

    // epilogue: bias + ReLU + fused 2x2 maxpool via atomicMax (values >= 0)
    unsigned* outp = (unsigned*)outpool;
#pragma unroll
    for (int mt = 0; mt < 4; mt++) {
#pragma unroll
        for (int nt = 0; nt < 4; nt++) {
            int col = n0 + wc * 32 + nt * 8 + (lane & 3) * 2;
            float b0v = bias[col], b1v = bias[col + 1];
#pragma unroll
            for (int h8 = 0; h8 < 2; h8++) {
                int m = m0 + wr * 64 + mt * 16 + (lane >> 2) + h8 * 8;
                int img = m / 196;
                int p = m % 196;
                int py = (p / 14) >> 1;
                int px = (p % 14) >> 1;
                size_t base = (size_t)((img * 7 + py) * 7 + px) * 256 + col;
                float v0 = fmaxf(acc[mt][nt][h8 * 2] + b0v, 0.f);
                float v1 = fmaxf(acc[mt][nt][h8 * 2 + 1] + b1v, 0.f);
                atomicMax(outp + base, __float_as_uint(v0));
                atomicMax(outp + base + 1, __float_as_uint(v1));
            }
        }
    }
}

// ============== decoder HMMA: parity classes, K in {2304,1536,1536,1024} ==========
__global__ __launch_bounds__(256, 1) void k_hmma_dec(
    const __half* __restrict__ a0p, const __half* __restrict__ a1p,
    const __half* __restrict__ b0p, const __half* __restrict__ b1p,
    const float* __restrict__ bias, float* __restrict__ out) {
    constexpr int STAGE = 65536;
    extern __shared__ __align__(1024) char smem[];
    const uint32_t sb = smem_to_u32(smem);
    const int t = threadIdx.x;
    const int wid = t >> 5;
    const int lane = t & 31;
    const int wr = wid & 1;
    const int wc = wid >> 1;
    const int m0 = blockIdx.x * 128;
    const int n0 = blockIdx.y * 128;
    const int cls = blockIdx.z;
    const int py = cls >> 1, px = cls & 1;
    const int TX = 3 - px;
    const int TY = 3 - py;
    const int nst = TY * TX * 4;
    const int Kc = TY * TX * 256;
    const int woff = (cls == 0) ? 0 : (cls == 1) ? 589824 : (cls == 2) ? 983040
                                                                       : 1376256;

    const int rr = t >> 3;
    const int seg = t & 7;
    int imgA[4], syA[4], sxA[4];
    uint32_t stsO[4];
#pragma unroll
    for (int j = 0; j < 4; j++) {
        int m = m0 + rr + 32 * j;
        imgA[j] = m / 49;
        int p = m % 49;
        syA[j] = p / 7;
        sxA[j] = p % 7;
        stsO[j] = SWZ((uint32_t)((rr + 32 * j) * 128 + seg * 16));
    }

    float acc[4][4][4];
#pragma unroll
    for (int i = 0; i < 4; i++)
#pragma unroll
        for (int j = 0; j < 4; j++)
#pragma unroll
            for (int q = 0; q < 4; q++) acc[i][j][q] = 0.f;

    const int arow = wr * 64 + (lane & 15);
    const uint32_t acolbase = (uint32_t)((lane >> 4) * 16);
    const int brow = wc * 32 + (lane & 7) + (lane >> 4) * 8;
    const uint32_t bcolbase = (uint32_t)(((lane >> 3) & 1) * 16);

    auto issue = [&](int s, int buf) {
        const int tap = s >> 2;
        const int ch0 = (s & 3) * 64;
        const int ty = tap / TX, tx = tap % TX;
        const uint32_t sbuf = sb + (uint32_t)buf * STAGE;
#pragma unroll
        for (int j = 0; j < 4; j++) {
            int iy = syA[j] + ty + (py - 1);
            int ix = sxA[j] + tx + (px - 1);
            bool v = ((unsigned)iy < 7u) && ((unsigned)ix < 7u);
            int pos = imgA[j] * 49 + iy * 7 + ix;
            int aoff = v ? (pos * 256 + ch0 + seg * 8) : 0;
            uint32_t sz = v ? 16u : 0u;
            cp_async16(sbuf + stsO[j], a0p + aoff, sz);
            cp_async16(sbuf + 16384 + stsO[j], a1p + aoff, sz);
            size_t boff = (size_t)woff + (size_t)(n0 + rr + 32 * j) * Kc + s * 64 +
                          seg * 8;
            cp_async16(sbuf + 32768 + stsO[j], b0p + boff, 16u);
            cp_async16(sbuf + 49152 + stsO[j], b1p + boff, 16u);
        }
    };

    issue(0, 0);
    CP_COMMIT();
    issue(1, 1);
    CP_COMMIT();

    int buf = 0;
    for (int s = 0; s < nst; s++) {
        if (s + 2 < nst) {
            int nb = buf + 2;
            if (nb >= 3) nb -= 3;
            issue(s + 2, nb);
            CP_COMMIT();
            CP_WAIT2();
        } else if (s + 1 < nst) {
            CP_WAIT1();
        } else {
            CP_WAIT0();
        }
        __syncthreads();

        const uint32_t abase = sb + (uint32_t)buf * STAGE;
        const uint32_t bbase = abase + 32768;
#pragma unroll
        for (int kk = 0; kk < 4; kk++) {
            uint32_t af[2][4][4];
            uint32_t bf[2][2][4];
            const uint32_t acol = acolbase + kk * 32;
#pragma unroll
            for (int la = 0; la < 2; la++)
#pragma unroll
                for (int mt = 0; mt < 4; mt++) {
                    int row = arow + mt * 16;
                    uint32_t addr =
                        abase + la * 16384 + row * 128 + (acol ^ ((row & 7) * 16));
                    LDSM4(af[la][mt][0], af[la][mt][1], af[la][mt][2], af[la][mt][3],
                          addr);
                }
            const uint32_t bcol = bcolbase + kk * 32;
#pragma unroll
            for (int lb = 0; lb < 2; lb++)
#pragma unroll
                for (int nt2 = 0; nt2 < 2; nt2++) {
                    int row = brow + nt2 * 16;
                    uint32_t addr =
                        bbase + lb * 16384 + row * 128 + (bcol ^ ((row & 7) * 16));
                    LDSM4(bf[lb][nt2][0], bf[lb][nt2][1], bf[lb][nt2][2],
                          bf[lb][nt2][3], addr);
                }
#pragma unroll
            for (int p = 0; p < 3; p++) {
                const int la = (p == 2) ? 1 : 0;
                const int lb = (p == 1) ? 1 : 0;
#pragma unroll
                for (int mt = 0; mt < 4; mt++)
#pragma unroll
                    for (int nt = 0; nt < 4; nt++)
                        mma16816(acc[mt][nt], af[la][mt],
                                 bf[lb][nt >> 1][(nt & 1) * 2],
                                 bf[lb][nt >> 1][(nt & 1) * 2 + 1]);
            }
        }
        __syncthreads();
        if (++buf == 3) buf = 0;
    }

    // epilogue: scatter rows back to the 14x14 grid, bias + ReLU
#pragma unroll
    for (int mt = 0; mt < 4; mt++) {
#pragma unroll
        for (int nt = 0; nt < 4; nt++) {
            int col = n0 + wc * 32 + nt * 8 + (lane & 3) * 2;
            float b0v = bias[col], b1v = bias[col + 1];
#pragma unroll
            for (int half8 = 0; half8 < 2; half8++) {
                int m = m0 + wr * 64 + mt * 16 + (lane >> 2) + half8 * 8;
                int img = m / 49;
                int p = m % 49;
                int oy = 2 * (p / 7) + py;
                int ox = 2 * (p % 7) + px;
                float2 v;
                v.x = fmaxf(acc[mt][nt][half8 * 2] + b0v, 0.f);
                v.y = fmaxf(acc[mt][nt][half8 * 2 + 1] + b1v, 0.f);
                *(float2*)(out + (size_t)((img * 14 + oy) * 14 + ox) * 256 + col) = v;
            }
        }
    }
}

// ---------------- K4: encoder FC split-K ----------------
__global__ __launch_bounds__(256) void k_enc_part(const float* __restrict__ h2,
                                                  const float* __restrict__ ew) {
    int kc = blockIdx.x;
    int b0 = blockIdx.y * 64;
    __shared__ float As[8][64];
    __shared__ float Bs[8][64];
    int t = threadIdx.x;
    int abb = t >> 2, akk = (t & 3) * 2;
    int bkk = t >> 5, bll = (t & 31) * 2;
    int tr = t >> 4, tc = t & 15;
    float acc[4][4] = {};
    int kbase = kc * 784;
    for (int ks = 0; ks < 784; ks += 8) {
        int k0 = kbase + ks;
        float2 av = *(const float2*)&h2[(b0 + abb) * 12544 + k0 + akk];
        float2 bv = *(const float2*)&ew[(k0 + bkk) * 64 + bll];
        __syncthreads();
        As[akk][abb] = av.x;
        As[akk + 1][abb] = av.y;
        *(float2*)&Bs[bkk][bll] = bv;
        __syncthreads();
#pragma unroll
        for (int kk = 0; kk < 8; kk++) {
            float a[4], b[4];
#pragma unroll
            for (int i = 0; i < 4; i++) a[i] = As[kk][tr * 4 + i];
#pragma unroll
            for (int j = 0; j < 4; j++) b[j] = Bs[kk][tc * 4 + j];
#pragma unroll
            for (int i = 0; i < 4; i++)
#pragma unroll
                for (int j = 0; j < 4; j++) acc[i][j] += a[i] * b[j];
        }
    }
#pragma unroll
    for (int i = 0; i < 4; i++)
#pragma unroll
        for (int j = 0; j < 4; j++)
            g_encp[(kc * 256 + b0 + tr * 4 + i) * 64 + tc * 4 + j] = acc[i][j];
}

__global__ void k_enc_reduce(const float* __restrict__ eb) {
    int idx = blockIdx.x * 256 + threadIdx.x;
    if (idx >= 256 * 64) return;
    float s = eb[idx & 63];
#pragma unroll
    for (int kc = 0; kc < 16; kc++) s += g_encp[kc * 16384 + idx];
    g_z[idx] = s;
}

// ---------------- K5: argmin + gather z_q ----------------
__global__ __launch_bounds__(256) void k_argmin(const float* __restrict__ emb) {
    int b = blockIdx.x;
    __shared__ float zb[64];
    __shared__ float ds[256];
    __shared__ int ki[256];
    int t = threadIdx.x;
    if (t < 64) zb[t] = g_z[b * 64 + t];
    __syncthreads();
    float d = 0.f;
    const float* e = emb + t * 64;
#pragma unroll 8
    for (int j = 0; j < 64; j++) {
        float df = zb[j] - e[j];
        d += df * df;
    }
    ds[t] = d;
    ki[t] = t;
    __syncthreads();
    for (int s = 128; s > 0; s >>= 1) {
        if (t < s) {
            float d2 = ds[t + s];
            int k2 = ki[t + s];
            if (d2 < ds[t] || (d2 == ds[t] && k2 < ki[t])) { ds[t] = d2; ki[t] = k2; }
        }
        __syncthreads();
    }
    int kb = ki[0];
    if (t < 64) g_z[(256 + b) * 64 + t] = emb[kb * 64 + t];
}

// ---------------- K6: decoder FC -> 2 fp16 limb planes ----------------
__global__ __launch_bounds__(256) void k_decfc(const float* __restrict__ dw,
                                               const float* __restrict__ db) {
    int n0 = blockIdx.x * 128;
    int m0 = blockIdx.y * 64;
    __shared__ float Zs[64][64];
    __shared__ float Bs[32][128];
    int t = threadIdx.x;
    {
        int rr = t >> 2, kk0 = (t & 3) * 16;
        const float* zp = &g_z[(m0 + rr) * 64 + kk0];
#pragma unroll
        for (int q = 0; q < 4; q++) {
            float4 v = *(const float4*)(zp + q * 4);
            Zs[kk0 + q * 4 + 0][rr] = v.x; Zs[kk0 + q * 4 + 1][rr] = v.y;
            Zs[kk0 + q * 4 + 2][rr] = v.z; Zs[kk0 + q * 4 + 3][rr] = v.w;
        }
    }
    int tr = t >> 5;
    int tc = t & 31;
    float acc[8][4] = {};
    for (int khf = 0; khf < 2; khf++) {
        __syncthreads();
        {
            int nn = (t & 31) * 4;
            int kk = t >> 5;
#pragma unroll
            for (int q = 0; q < 4; q++) {
                int row = kk + q * 8;
                *(float4*)&Bs[row][nn] =
                    *(const float4*)&dw[(khf * 32 + row) * 12544 + n0 + nn];
            }
        }
        __syncthreads();
#pragma unroll
        for (int kk = 0; kk < 32; kk++) {
            int kg = khf * 32 + kk;
            float a[8];
#pragma unroll
            for (int i = 0; i < 8; i++) a[i] = Zs[kg][tr * 8 + i];
            float4 b4 = *(const float4*)&Bs[kk][tc * 4];
            float bb[4] = {b4.x, b4.y, b4.z, b4.w};
#pragma unroll
            for (int i = 0; i < 8; i++)
#pragma unroll
                for (int j = 0; j < 4; j++) acc[i][j] += a[i] * bb[j];
        }
    }
#pragma unroll
    for (int i = 0; i < 8; i++) {
        int m = m0 + tr * 8 + i;
#pragma unroll
        for (int j = 0; j < 4; j++) {
            int f = n0 + tc * 4 + j;
            float v = acc[i][j] + db[f];
            size_t idx = (size_t)m * 12544 + f;
            __half h = __float2half(v);
            g_dh[idx] = h;
            g_dl[idx] = __float2half(v - __half2float(h));
        }
    }
}

// ---------------- K8: deconv2 + sigmoid ----------------
__global__ __launch_bounds__(256) void k_deconv2(const float* __restrict__ w2,
                                                 const float* __restrict__ b2,
                                                 float* __restrict__ out) {
    int img = blockIdx.x;
    int half = blockIdx.y;
    int y0 = half * 14;
    int gbase = half * 6;
    __shared__ float gs[8][14][64];
    __shared__ float ws[16][64];
    __shared__ float pacc[392];
    int t = threadIdx.x;
    int wrp = t >> 5, lane = t & 31;
    pacc[t] = 0.f;
    if (t < 136) pacc[256 + t] = 0.f;
    float bias = b2[0];
    for (int cc = 0; cc < 4; cc++) {
        __syncthreads();
        for (int e = t; e < 8 * 14 * 64; e += 256) {
            int c = e & 63, xx = (e >> 6) % 14, r = e / 896;
            gs[r][xx][c] = g_g1[((img * 14 + gbase + r) * 14 + xx) * 256 + cc * 64 + c];
        }
        for (int e = t; e < 1024; e += 256) {
            int c = e & 63, tap = e >> 6;
            ws[tap][c] = w2[tap * 256 + cc * 64 + c];
        }
        __syncthreads();
        for (int p = wrp; p < 392; p += 8) {
            int yy = p / 28, x = p % 28;
            int y = y0 + yy;
            float r = 0.f;
#pragma unroll
            for (int ky = 0; ky < 4; ky++) {
                int uy = y - 1 + ky;
                if ((unsigned)uy >= 28u) continue;
                int gy = (uy >> 1) - gbase;
#pragma unroll
                for (int kx = 0; kx < 4; kx++) {
                    int ux = x - 1 + kx;
                    if ((unsigned)ux >= 28u) continue;
                    int gx = ux >> 1;
                    const float* gp = &gs[gy][gx][0];
                    const float* wp = &ws[ky * 4 + kx][0];
                    r += gp[lane] * wp[lane] + gp[lane + 32] * wp[lane + 32];
                }
            }
#pragma unroll
            for (int s = 16; s > 0; s >>= 1) r += __shfl_xor_sync(0xffffffffu, r, s);
            if (lane == 0) pacc[p] += r;
        }
    }
    __syncthreads();
    for (int p = t; p < 392; p += 256) {
        int yy = p / 28, x = p % 28;
        float v = pacc[p] + bias;
        out[img * 784 + (y0 + yy) * 28 + x] = 1.f / (1.f + expf(-v));
    }
}

// ---------------- launch ----------------
static constexpr int SMEM_HMMA = 3 * 65536;  // 196608

extern "C" void kernel_launch(void* const* d_in, const int* in_sizes, int n_in,
                              void* d_out, int out_size) {
    const float* x   = (const float*)d_in[0];
    const float* c1w = (const float*)d_in[1];
    const float* c1b = (const float*)d_in[2];
    const float* c2w = (const float*)d_in[3];
    const float* c2b = (const float*)d_in[4];
    const float* ew  = (const float*)d_in[5];
    const float* eb  = (const float*)d_in[6];
    const float* emb = (const float*)d_in[7];
    const float* dw  = (const float*)d_in[8];
    const float* db  = (const float*)d_in[9];
    const float* d1w = (const float*)d_in[10];
    const float* d1b = (const float*)d_in[11];
    const float* d2w = (const float*)d_in[12];
    const float* d2b = (const float*)d_in[13];
    float* out = (float*)d_out;

    void *pa1h, *pa1l, *pw2h, *pw2l, *pdh, *pdl, *pw1h, *pw1l, *ph2, *pg1;
    cudaGetSymbolAddress(&pa1h, g_a1h);
    cudaGetSymbolAddress(&pa1l, g_a1l);
    cudaGetSymbolAddress(&pw2h, g_w2h);
    cudaGetSymbolAddress(&pw2l, g_w2l);
    cudaGetSymbolAddress(&pdh, g_dh);
    cudaGetSymbolAddress(&pdl, g_dl);
    cudaGetSymbolAddress(&pw1h, g_w1h);
    cudaGetSymbolAddress(&pw1l, g_w1l);
    cudaGetSymbolAddress(&ph2, g_h2);
    cudaGetSymbolAddress(&pg1, g_g1);

    cudaFuncSetAttribute((const void*)k_hmma_enc,
                         cudaFuncAttributeMaxDynamicSharedMemorySize, SMEM_HMMA);
    cudaFuncSetAttribute((const void*)k_hmma_dec,
                         cudaFuncAttributeMaxDynamicSharedMemorySize, SMEM_HMMA);

    k_zero_h2<<<3136, 256>>>();
    k_conv1pool<<<dim3(14, 256), 256>>>(x, c1w, c1b);
    k_wsplit2<<<dim3(128, 8), 256>>>(c2w, (__half*)pw2h, (__half*)pw2l);
    k_wcomb<<<(1638400 + 255) / 256, 256>>>(d1w, (__half*)pw1h, (__half*)pw1l);
    k_hmma_enc<<<dim3(392, 2), 256, SMEM_HMMA>>>(
        (const __half*)pa1h, (const __half*)pa1l, (const __half*)pw2h,
        (const __half*)pw2l, c2b, (float*)ph2);
    k_enc_part<<<dim3(16, 4), 256>>>((const float*)ph2, ew);
    k_enc_reduce<<<64, 256>>>(eb);
    k_argmin<<<256, 256>>>(emb);
    k_decfc<<<dim3(98, 8), 256>>>(dw, db);
    k_hmma_dec<<<dim3(196, 2, 4), 256, SMEM_HMMA>>>(
        (const __half*)pdh, (const __half*)pdl, (const __half*)pw1h,
        (const __half*)pw1l, d1b, (float*)pg1);
    k_deconv2<<<dim3(512, 2), 256>>>(d2w, d2b, out);
}